// round 1
// baseline (speedup 1.0000x reference)
#include <cuda_runtime.h>
#include <cuda_bf16.h>
#include <math.h>

// Problem constants (fixed by setup_inputs): N=1024, B=64, C=256, h=8, hd=32,
// H=W=32, SR=2 -> Hs=Ws=16, Ns=256.
#define NN 1024
#define BB 64
#define CC 256
#define NHEAD 8
#define HD 32
#define NS 256
#define PI_OVER_64 0.04908738521234052f   // (pi/2)/32
#define PI_OVER_32 0.09817477042468103f   // (pi/2)/16
#define QSCALE 0.17677669529663687f       // 32^-0.5

// ---------------- device scratch (allocation-free: module-load static) -------
__device__ float g_xr[BB * NS * CC];          // conv output -> layernormed (B,Ns,C)
__device__ float g_q[BB * NN * CC];           // q projection, relu'd (B,N,C)
__device__ float g_kb[BB * NS * CC];          // k projection, relu'd
__device__ float g_vb[BB * NS * CC];          // v projection
__device__ float g_kv[BB * NHEAD * 128 * 32]; // per (b,h): kv[d=t*32+j][m]
__device__ float g_ksum[BB * NHEAD * 128];    // per (b,h): ksum[d]
__device__ float g_attn[BB * NN * CC];        // attention output (B,N,C)
__device__ float g_wt[CC * 1024];             // conv weights permuted (O, dd, I)
__device__ float g_se[BB * CC];               // SE gate
__device__ float g_sein[BB * CC];             // mean over N

// ---------------- small kernels ----------------------------------------------
__global__ void wtrans_kernel(const float* __restrict__ srw, float* __restrict__ wt)
{
    int idx = blockIdx.x * 256 + threadIdx.x;   // 256*1024 elems, grid 1024
    int o = idx >> 10, rest = idx & 1023;
    int dd = rest >> 8, i = rest & 255;
    wt[idx] = srw[(o << 10) + (i << 2) + dd];
}

__global__ void se_mean_kernel(const float* __restrict__ query, float* __restrict__ sein)
{
    int idx = blockIdx.x * 256 + threadIdx.x;   // 16384 (b*C+c), grid 64
    float s = 0.f;
    #pragma unroll 8
    for (int n = 0; n < NN; n++) s += query[(size_t)n * (BB * CC) + idx];
    sein[idx] = s * (1.0f / (float)NN);
}

__global__ void se_mlp_kernel(const float* __restrict__ sein,
                              const float* __restrict__ w1,
                              const float* __restrict__ w2,
                              float* __restrict__ se)
{
    int b = blockIdx.x;
    int tid = threadIdx.x;                       // 256
    __shared__ float xin[256];
    __shared__ float hid[128];
    xin[tid] = sein[b * 256 + tid];
    __syncthreads();
    if (tid < 128) {
        float s = 0.f;
        #pragma unroll 8
        for (int c = 0; c < 256; c++) s += xin[c] * w1[tid * 256 + c];
        hid[tid] = fmaxf(s, 0.f);
    }
    __syncthreads();
    float s = 0.f;
    #pragma unroll 8
    for (int r = 0; r < 128; r++) s += hid[r] * w2[tid * 128 + r];
    se[b * 256 + tid] = 1.f / (1.f + expf(-s));
}

__global__ void ln_kernel(float* __restrict__ x,
                          const float* __restrict__ gg,
                          const float* __restrict__ bb)
{
    int row = blockIdx.x * 8 + (threadIdx.x >> 5);   // 16384 rows of 256
    int lane = threadIdx.x & 31;
    float* xr = x + (size_t)row * 256;
    float4 v0 = ((float4*)xr)[lane];
    float4 v1 = ((float4*)xr)[32 + lane];
    float s  = v0.x + v0.y + v0.z + v0.w + v1.x + v1.y + v1.z + v1.w;
    float sq = v0.x*v0.x + v0.y*v0.y + v0.z*v0.z + v0.w*v0.w
             + v1.x*v1.x + v1.y*v1.y + v1.z*v1.z + v1.w*v1.w;
    #pragma unroll
    for (int o = 16; o > 0; o >>= 1) {
        s  += __shfl_xor_sync(0xffffffffu, s,  o);
        sq += __shfl_xor_sync(0xffffffffu, sq, o);
    }
    float mean = s * (1.f / 256.f);
    float var  = sq * (1.f / 256.f) - mean * mean;
    float rstd = rsqrtf(var + 1e-5f);
    const float4 gA = ((const float4*)gg)[lane];
    const float4 gB = ((const float4*)gg)[32 + lane];
    const float4 bA = ((const float4*)bb)[lane];
    const float4 bB = ((const float4*)bb)[32 + lane];
    float4 r0, r1;
    r0.x = (v0.x - mean) * rstd * gA.x + bA.x;
    r0.y = (v0.y - mean) * rstd * gA.y + bA.y;
    r0.z = (v0.z - mean) * rstd * gA.z + bA.z;
    r0.w = (v0.w - mean) * rstd * gA.w + bA.w;
    r1.x = (v1.x - mean) * rstd * gB.x + bB.x;
    r1.y = (v1.y - mean) * rstd * gB.y + bB.y;
    r1.z = (v1.z - mean) * rstd * gB.z + bB.z;
    r1.w = (v1.w - mean) * rstd * gB.w + bB.w;
    ((float4*)xr)[lane] = r0;
    ((float4*)xr)[32 + lane] = r1;
}

// ---------------- kv aggregation: kv[t*32+j][m], ksum[t*32+j] ----------------
__global__ void __launch_bounds__(128) kv_kernel(const float* __restrict__ kbuf,
                                                 const float* __restrict__ vbuf,
                                                 float* __restrict__ kvout,
                                                 float* __restrict__ ksumout)
{
    const int bh = blockIdx.x;                 // 512
    const int b = bh >> 3, hh = bh & 7;
    const int tid = threadIdx.x;               // 128
    const int t = tid >> 5, j = tid & 31;
    __shared__ float ksh[8][32];
    __shared__ float vsh[8][32];
    __shared__ float wsh[8][4];
    float acc[32];
    #pragma unroll
    for (int m = 0; m < 32; m++) acc[m] = 0.f;
    float kssum = 0.f;
    const float* kbase = kbuf + (size_t)b * NS * CC + hh * 32;
    const float* vbase = vbuf + (size_t)b * NS * CC + hh * 32;

    for (int s0 = 0; s0 < NS; s0 += 8) {
        {
            int idx = tid & 63, sr = idx >> 3, c4 = idx & 7;
            const float* src = (tid < 64 ? kbase : vbase) + (size_t)(s0 + sr) * CC + c4 * 4;
            float4 v = *(const float4*)src;
            float* dst = (tid < 64) ? &ksh[sr][c4 * 4] : &vsh[sr][c4 * 4];
            dst[0] = v.x; dst[1] = v.y; dst[2] = v.z; dst[3] = v.w;
        }
        if (tid < 32) {
            int sr2 = tid >> 2, tt = tid & 3;
            int s = s0 + sr2;
            float ang = ((tt < 2) ? (float)(s >> 4) : (float)(s & 15)) * PI_OVER_32;
            float sn, cs; sincosf(ang, &sn, &cs);
            wsh[sr2][tt] = (tt & 1) ? sn : cs;
        }
        __syncthreads();
        #pragma unroll
        for (int sr2 = 0; sr2 < 8; sr2++) {
            float kw = ksh[sr2][j] * wsh[sr2][t];
            kssum += kw;
            #pragma unroll
            for (int m4 = 0; m4 < 8; m4++) {
                float4 vv = *(const float4*)&vsh[sr2][m4 * 4];
                acc[m4 * 4 + 0] += kw * vv.x;
                acc[m4 * 4 + 1] += kw * vv.y;
                acc[m4 * 4 + 2] += kw * vv.z;
                acc[m4 * 4 + 3] += kw * vv.w;
            }
        }
        __syncthreads();
    }
    float* kvdst = kvout + ((size_t)bh * 128 + tid) * 32;
    #pragma unroll
    for (int m4 = 0; m4 < 8; m4++) {
        float4 v;
        v.x = acc[m4 * 4 + 0]; v.y = acc[m4 * 4 + 1];
        v.z = acc[m4 * 4 + 2]; v.w = acc[m4 * 4 + 3];
        *(float4*)(kvdst + m4 * 4) = v;
    }
    ksumout[(size_t)bh * 128 + tid] = kssum;
}

// ---------------- attention: attn[n][m] per (b,h) ----------------------------
__global__ void __launch_bounds__(256) attn_kernel(const float* __restrict__ q,
                                                   const float* __restrict__ kv,
                                                   const float* __restrict__ ksum,
                                                   float* __restrict__ attn)
{
    const int bh = blockIdx.y;                  // 512
    const int b = bh >> 3, hh = bh & 7;
    const int n0 = blockIdx.x * 64;             // 16 tiles
    const int tid = threadIdx.x;                // 256
    const int m = tid & 31, r = tid >> 5;       // r in 0..7

    __shared__ float q_sh[64][36];
    __shared__ float kvT[4][32][36];            // [t][m][j], stride 36 -> conflict-free
    __shared__ float ksum_sh[4][32];
    __shared__ float dp_sh[64][4];

    const float* qbase = q + ((size_t)(b * NN + n0)) * CC + hh * 32;
    #pragma unroll
    for (int p = 0; p < 2; p++) {
        int slot = p * 256 + tid;               // 0..511
        int nl = slot >> 3, jc = slot & 7;
        float4 v = *(const float4*)(qbase + (size_t)nl * CC + jc * 4);
        q_sh[nl][jc * 4 + 0] = v.x;
        q_sh[nl][jc * 4 + 1] = v.y;
        q_sh[nl][jc * 4 + 2] = v.z;
        q_sh[nl][jc * 4 + 3] = v.w;
    }
    const float* kvbase = kv + (size_t)bh * 128 * 32;
    #pragma unroll
    for (int p = 0; p < 4; p++) {
        int slot = p * 256 + tid;               // 0..1023
        int d = slot >> 3, mc = slot & 7;
        float4 v = *(const float4*)(kvbase + d * 32 + mc * 4);
        int t = d >> 5, j = d & 31;
        kvT[t][mc * 4 + 0][j] = v.x;
        kvT[t][mc * 4 + 1][j] = v.y;
        kvT[t][mc * 4 + 2][j] = v.z;
        kvT[t][mc * 4 + 3][j] = v.w;
    }
    if (tid < 128) ksum_sh[tid >> 5][tid & 31] = ksum[(size_t)bh * 128 + tid];
    __syncthreads();

    {   // denominator partials: dp[nl][t] = q[nl] . ksum_t
        int nl = tid >> 2, t = tid & 3;
        float s = 0.f;
        #pragma unroll
        for (int j = 0; j < 32; j++) s += q_sh[nl][j] * ksum_sh[t][j];
        dp_sh[nl][t] = s;
    }
    __syncthreads();

    float acc[8][4];
    #pragma unroll
    for (int s = 0; s < 8; s++)
        #pragma unroll
        for (int t = 0; t < 4; t++) acc[s][t] = 0.f;

    #pragma unroll
    for (int j4 = 0; j4 < 8; j4++) {
        float4 kq[4];
        #pragma unroll
        for (int t = 0; t < 4; t++) kq[t] = *(const float4*)&kvT[t][m][j4 * 4];
        #pragma unroll
        for (int s = 0; s < 8; s++) {
            int nl = r * 8 + s;
            float4 qv = *(const float4*)&q_sh[nl][j4 * 4];
            #pragma unroll
            for (int t = 0; t < 4; t++) {
                acc[s][t] += qv.x * kq[t].x + qv.y * kq[t].y
                           + qv.z * kq[t].z + qv.w * kq[t].w;
            }
        }
    }

    #pragma unroll
    for (int s = 0; s < 8; s++) {
        int nl = r * 8 + s;
        int n = n0 + nl;
        float sa, ca, sb, cb;
        sincosf((float)(n >> 5) * PI_OVER_64, &sa, &ca);
        sincosf((float)(n & 31) * PI_OVER_64, &sb, &cb);
        float den = ca * dp_sh[nl][0] + sa * dp_sh[nl][1]
                  + cb * dp_sh[nl][2] + sb * dp_sh[nl][3];
        float ad = fminf(fmaxf(fabsf(den), 1e-4f), 1e4f);
        den = (den < 0.f) ? -ad : ad;
        float num = ca * acc[s][0] + sa * acc[s][1]
                  + cb * acc[s][2] + sb * acc[s][3];
        attn[((size_t)(b * NN + n)) * CC + hh * 32 + m] = num / den;
    }
}

// ---------------- tiled SGEMM: out = A(MxK) @ Bw(NxK)^T + bias, epilogues ----
// AMODE: 0 plain row-major A
//        1 A is query read transposed: m=(b,n) -> query[n][b][k]
//        2 A is implicit conv patches from query: m=(b,ns), k=(dd,i)
// EMODE: 0 +bias; 1 +bias,relu; 2 (+bias)*QSCALE,relu; 3 out-proj (se mul + transposed store)
template<int AMODE>
__device__ __forceinline__ const float* a_index(const float* __restrict__ A, int m, int k, int K)
{
    if (AMODE == 0) {
        return A + (size_t)m * K + k;
    } else if (AMODE == 1) {
        return A + (size_t)(m & (NN - 1)) * (BB * CC) + (m >> 10) * CC + k;
    } else {
        int b = m >> 8, ns = m & 255;
        int dd = k >> 8, i = k & 255;
        int pos = (((ns >> 4) * 2 + (dd >> 1)) << 5) + ((ns & 15) * 2 + (dd & 1));
        return A + (size_t)pos * (BB * CC) + b * CC + i;
    }
}

template<int AMODE, int EMODE>
__global__ void __launch_bounds__(256) sgemm_kernel(
    const float* __restrict__ A, const float* __restrict__ Bw,
    const float* __restrict__ bias, float* __restrict__ Cout,
    int M, int N, int K,
    const float* __restrict__ se, float* __restrict__ dout)
{
    __shared__ float As[16][132];
    __shared__ float Bs[16][132];
    const int tid = threadIdx.x;
    const int tx = tid & 15, ty = tid >> 4;
    const int m0 = blockIdx.x * 128;
    const int n0 = blockIdx.y * 128;

    float acc[8][8];
    #pragma unroll
    for (int i = 0; i < 8; i++)
        #pragma unroll
        for (int j = 0; j < 8; j++) acc[i][j] = 0.f;

    for (int kt = 0; kt < K; kt += 16) {
        #pragma unroll
        for (int p = 0; p < 2; p++) {
            int slot = p * 256 + tid;
            int mm = slot >> 2, kc = slot & 3;
            float4 v = *(const float4*)a_index<AMODE>(A, m0 + mm, kt + kc * 4, K);
            As[kc * 4 + 0][mm] = v.x;
            As[kc * 4 + 1][mm] = v.y;
            As[kc * 4 + 2][mm] = v.z;
            As[kc * 4 + 3][mm] = v.w;
        }
        #pragma unroll
        for (int p = 0; p < 2; p++) {
            int slot = p * 256 + tid;
            int nn = slot >> 2, kc = slot & 3;
            float4 v = *(const float4*)(Bw + (size_t)(n0 + nn) * K + kt + kc * 4);
            Bs[kc * 4 + 0][nn] = v.x;
            Bs[kc * 4 + 1][nn] = v.y;
            Bs[kc * 4 + 2][nn] = v.z;
            Bs[kc * 4 + 3][nn] = v.w;
        }
        __syncthreads();
        #pragma unroll
        for (int kk = 0; kk < 16; kk++) {
            float4 a0 = *(const float4*)&As[kk][ty * 8];
            float4 a1 = *(const float4*)&As[kk][ty * 8 + 4];
            float4 b0 = *(const float4*)&Bs[kk][tx * 8];
            float4 b1 = *(const float4*)&Bs[kk][tx * 8 + 4];
            float av[8] = {a0.x, a0.y, a0.z, a0.w, a1.x, a1.y, a1.z, a1.w};
            float bv[8] = {b0.x, b0.y, b0.z, b0.w, b1.x, b1.y, b1.z, b1.w};
            #pragma unroll
            for (int i = 0; i < 8; i++)
                #pragma unroll
                for (int j = 0; j < 8; j++)
                    acc[i][j] += av[i] * bv[j];
        }
        __syncthreads();
    }

    const int mb = m0 + ty * 8;
    const int nb = n0 + tx * 8;
    if (EMODE == 3) {
        #pragma unroll
        for (int i = 0; i < 8; i++) {
            int mrow = mb + i;
            int b = mrow >> 10, nseq = mrow & (NN - 1);
            float* drow = dout + ((size_t)nseq * BB + b) * CC;
            float4 o0, o1;
            float* po = &o0.x;
            #pragma unroll
            for (int j = 0; j < 8; j++) {
                int n = nb + j;
                float v = (acc[i][j] + bias[n]) * se[b * CC + n];
                if (j < 4) (&o0.x)[j] = v; else (&o1.x)[j - 4] = v;
            }
            (void)po;
            *(float4*)(drow + nb) = o0;
            *(float4*)(drow + nb + 4) = o1;
        }
    } else {
        #pragma unroll
        for (int i = 0; i < 8; i++) {
            float* crow = Cout + (size_t)(mb + i) * N;
            float4 o0, o1;
            #pragma unroll
            for (int j = 0; j < 8; j++) {
                int n = nb + j;
                float v = acc[i][j] + bias[n];
                if (EMODE == 1) v = fmaxf(v, 0.f);
                if (EMODE == 2) v = fmaxf(v * QSCALE, 0.f);
                if (j < 4) (&o0.x)[j] = v; else (&o1.x)[j - 4] = v;
            }
            *(float4*)(crow + nb) = o0;
            *(float4*)(crow + nb + 4) = o1;
        }
    }
}

// ---------------- launch ------------------------------------------------------
extern "C" void kernel_launch(void* const* d_in, const int* in_sizes, int n_in,
                              void* d_out, int out_size)
{
    (void)in_sizes; (void)n_in; (void)out_size;
    const float* query = (const float*)d_in[0];
    // d_in[1]=H, d_in[2]=W (always 32), d_in[3]=key, d_in[4]=value : unused
    const float* ipw  = (const float*)d_in[5];
    const float* ipb  = (const float*)d_in[6];
    const float* srw  = (const float*)d_in[7];
    const float* srb  = (const float*)d_in[8];
    const float* ng   = (const float*)d_in[9];
    const float* nb   = (const float*)d_in[10];
    const float* outw = (const float*)d_in[11];
    const float* outb = (const float*)d_in[12];
    const float* sew1 = (const float*)d_in[13];
    const float* sew2 = (const float*)d_in[14];
    float* out = (float*)d_out;

    float *xr, *qb, *kb, *vb, *kv, *ks, *attn, *wt, *se, *sein;
    cudaGetSymbolAddress((void**)&xr,   g_xr);
    cudaGetSymbolAddress((void**)&qb,   g_q);
    cudaGetSymbolAddress((void**)&kb,   g_kb);
    cudaGetSymbolAddress((void**)&vb,   g_vb);
    cudaGetSymbolAddress((void**)&kv,   g_kv);
    cudaGetSymbolAddress((void**)&ks,   g_ksum);
    cudaGetSymbolAddress((void**)&attn, g_attn);
    cudaGetSymbolAddress((void**)&wt,   g_wt);
    cudaGetSymbolAddress((void**)&se,   g_se);
    cudaGetSymbolAddress((void**)&sein, g_sein);

    // SE path
    se_mean_kernel<<<64, 256>>>(query, sein);
    se_mlp_kernel<<<64, 256>>>(sein, sew1, sew2, se);

    // conv (as GEMM over implicit patches) + bias, then layernorm (in-place)
    wtrans_kernel<<<1024, 256>>>(srw, wt);
    sgemm_kernel<2, 0><<<dim3(128, 2), 256>>>(query, wt, srb, xr,
                                              BB * NS, CC, 1024, nullptr, nullptr);
    ln_kernel<<<2048, 256>>>(xr, ng, nb);

    // projections
    sgemm_kernel<1, 2><<<dim3(512, 2), 256>>>(query, ipw, ipb, qb,
                                              BB * NN, CC, CC, nullptr, nullptr);
    sgemm_kernel<0, 1><<<dim3(128, 2), 256>>>(xr, ipw + CC * CC, ipb + CC, kb,
                                              BB * NS, CC, CC, nullptr, nullptr);
    sgemm_kernel<0, 0><<<dim3(128, 2), 256>>>(xr, ipw + 2 * CC * CC, ipb + 2 * CC, vb,
                                              BB * NS, CC, CC, nullptr, nullptr);

    // cosformer linear attention
    kv_kernel<<<512, 128>>>(kb, vb, kv, ks);
    attn_kernel<<<dim3(16, 512), 256>>>(qb, kv, ks, attn);

    // output projection + SE gating + transpose to (N,B,C)
    sgemm_kernel<0, 3><<<dim3(512, 2), 256>>>(attn, outw, outb, nullptr,
                                              BB * NN, CC, CC, se, out);
}

// round 3
// speedup vs baseline: 1.7179x; 1.7179x over previous
#include <cuda_runtime.h>
#include <cuda_bf16.h>
#include <math.h>
#include <cstdint>

// Problem constants (fixed by setup_inputs): N=1024, B=64, C=256, h=8, hd=32,
// H=W=32, SR=2 -> Hs=Ws=16, Ns=256.
#define NN 1024
#define BB 64
#define CC 256
#define NHEAD 8
#define HD 32
#define NS 256
#define PI_OVER_64 0.04908738521234052f   // (pi/2)/32
#define PI_OVER_32 0.09817477042468103f   // (pi/2)/16
#define QSCALE 0.17677669529663687f       // 32^-0.5

typedef unsigned int u32;

// ---------------- device scratch (allocation-free: module-load static) -------
__device__ float g_xr[BB * NS * CC];          // conv output -> layernormed (B,Ns,C)
__device__ float g_q[BB * NN * CC];           // q projection, relu'd (B,N,C)
__device__ float g_kb[BB * NS * CC];          // k projection, relu'd
__device__ float g_vb[BB * NS * CC];          // v projection
__device__ float g_kv[BB * NHEAD * 128 * 32]; // per (b,h): kv[d=t*32+j][m]
__device__ float g_ksum[BB * NHEAD * 128];    // per (b,h): ksum[d]
__device__ float g_attn[BB * NN * CC];        // attention output (B,N,C)
__device__ float g_wt[CC * 1024];             // conv weights permuted (O, dd, I)
__device__ float g_se[BB * CC];               // SE gate
__device__ float g_sein[BB * CC];             // mean over N

// ---------------- helpers -----------------------------------------------------
__device__ __forceinline__ u32 f2tf32(float x)
{
    u32 r;
    asm("cvt.rna.tf32.f32 %0, %1;" : "=r"(r) : "f"(x));
    return r;
}

__device__ __forceinline__ void mma_tf32(float* c, const u32* a, const u32* b)
{
    asm volatile(
        "mma.sync.aligned.m16n8k8.row.col.f32.tf32.tf32.f32 "
        "{%0,%1,%2,%3}, {%4,%5,%6,%7}, {%8,%9}, {%0,%1,%2,%3};"
        : "+f"(c[0]), "+f"(c[1]), "+f"(c[2]), "+f"(c[3])
        : "r"(a[0]), "r"(a[1]), "r"(a[2]), "r"(a[3]),
          "r"(b[0]), "r"(b[1]));
}

// ---------------- small kernels ----------------------------------------------
__global__ void wtrans_kernel(const float* __restrict__ srw, float* __restrict__ wt)
{
    int idx = blockIdx.x * 256 + threadIdx.x;   // 256*1024 elems, grid 1024
    int o = idx >> 10, rest = idx & 1023;
    int dd = rest >> 8, i = rest & 255;
    wt[idx] = srw[(o << 10) + (i << 2) + dd];
}

__global__ void se_mean_kernel(const float* __restrict__ query, float* __restrict__ sein)
{
    int idx = blockIdx.x * 256 + threadIdx.x;   // 16384 (b*C+c), grid 64
    float s = 0.f;
    #pragma unroll 8
    for (int n = 0; n < NN; n++) s += query[(size_t)n * (BB * CC) + idx];
    sein[idx] = s * (1.0f / (float)NN);
}

__global__ void se_mlp_kernel(const float* __restrict__ sein,
                              const float* __restrict__ w1,
                              const float* __restrict__ w2,
                              float* __restrict__ se)
{
    int b = blockIdx.x;
    int tid = threadIdx.x;                       // 256
    __shared__ float xin[256];
    __shared__ float hid[128];
    xin[tid] = sein[b * 256 + tid];
    __syncthreads();
    if (tid < 128) {
        float s = 0.f;
        #pragma unroll 8
        for (int c = 0; c < 256; c++) s += xin[c] * w1[tid * 256 + c];
        hid[tid] = fmaxf(s, 0.f);
    }
    __syncthreads();
    float s = 0.f;
    #pragma unroll 8
    for (int r = 0; r < 128; r++) s += hid[r] * w2[tid * 128 + r];
    se[b * 256 + tid] = 1.f / (1.f + expf(-s));
}

__global__ void ln_kernel(float* __restrict__ x,
                          const float* __restrict__ gg,
                          const float* __restrict__ bb)
{
    int row = blockIdx.x * 8 + (threadIdx.x >> 5);   // 16384 rows of 256
    int lane = threadIdx.x & 31;
    float* xr = x + (size_t)row * 256;
    float4 v0 = ((float4*)xr)[lane];
    float4 v1 = ((float4*)xr)[32 + lane];
    float s  = v0.x + v0.y + v0.z + v0.w + v1.x + v1.y + v1.z + v1.w;
    float sq = v0.x*v0.x + v0.y*v0.y + v0.z*v0.z + v0.w*v0.w
             + v1.x*v1.x + v1.y*v1.y + v1.z*v1.z + v1.w*v1.w;
    #pragma unroll
    for (int o = 16; o > 0; o >>= 1) {
        s  += __shfl_xor_sync(0xffffffffu, s,  o);
        sq += __shfl_xor_sync(0xffffffffu, sq, o);
    }
    float mean = s * (1.f / 256.f);
    float var  = sq * (1.f / 256.f) - mean * mean;
    float rstd = rsqrtf(var + 1e-5f);
    const float4 gA = ((const float4*)gg)[lane];
    const float4 gB = ((const float4*)gg)[32 + lane];
    const float4 bA = ((const float4*)bb)[lane];
    const float4 bB = ((const float4*)bb)[32 + lane];
    float4 r0, r1;
    r0.x = (v0.x - mean) * rstd * gA.x + bA.x;
    r0.y = (v0.y - mean) * rstd * gA.y + bA.y;
    r0.z = (v0.z - mean) * rstd * gA.z + bA.z;
    r0.w = (v0.w - mean) * rstd * gA.w + bA.w;
    r1.x = (v1.x - mean) * rstd * gB.x + bB.x;
    r1.y = (v1.y - mean) * rstd * gB.y + bB.y;
    r1.z = (v1.z - mean) * rstd * gB.z + bB.z;
    r1.w = (v1.w - mean) * rstd * gB.w + bB.w;
    ((float4*)xr)[lane] = r0;
    ((float4*)xr)[32 + lane] = r1;
}

// ---------------- kv aggregation: kv[t*32+j][m], ksum[t*32+j] ----------------
__global__ void __launch_bounds__(128) kv_kernel(const float* __restrict__ kbuf,
                                                 const float* __restrict__ vbuf,
                                                 float* __restrict__ kvout,
                                                 float* __restrict__ ksumout)
{
    const int bh = blockIdx.x;                 // 512
    const int b = bh >> 3, hh = bh & 7;
    const int tid = threadIdx.x;               // 128
    const int t = tid >> 5, j = tid & 31;
    __shared__ float ksh[8][32];
    __shared__ float vsh[8][32];
    __shared__ float wsh[8][4];
    float acc[32];
    #pragma unroll
    for (int m = 0; m < 32; m++) acc[m] = 0.f;
    float kssum = 0.f;
    const float* kbase = kbuf + (size_t)b * NS * CC + hh * 32;
    const float* vbase = vbuf + (size_t)b * NS * CC + hh * 32;

    for (int s0 = 0; s0 < NS; s0 += 8) {
        {
            int idx = tid & 63, sr = idx >> 3, c4 = idx & 7;
            const float* src = (tid < 64 ? kbase : vbase) + (size_t)(s0 + sr) * CC + c4 * 4;
            float4 v = *(const float4*)src;
            float* dst = (tid < 64) ? &ksh[sr][c4 * 4] : &vsh[sr][c4 * 4];
            dst[0] = v.x; dst[1] = v.y; dst[2] = v.z; dst[3] = v.w;
        }
        if (tid < 32) {
            int sr2 = tid >> 2, tt = tid & 3;
            int s = s0 + sr2;
            float ang = ((tt < 2) ? (float)(s >> 4) : (float)(s & 15)) * PI_OVER_32;
            float sn, cs; sincosf(ang, &sn, &cs);
            wsh[sr2][tt] = (tt & 1) ? sn : cs;
        }
        __syncthreads();
        #pragma unroll
        for (int sr2 = 0; sr2 < 8; sr2++) {
            float kw = ksh[sr2][j] * wsh[sr2][t];
            kssum += kw;
            #pragma unroll
            for (int m4 = 0; m4 < 8; m4++) {
                float4 vv = *(const float4*)&vsh[sr2][m4 * 4];
                acc[m4 * 4 + 0] += kw * vv.x;
                acc[m4 * 4 + 1] += kw * vv.y;
                acc[m4 * 4 + 2] += kw * vv.z;
                acc[m4 * 4 + 3] += kw * vv.w;
            }
        }
        __syncthreads();
    }
    float* kvdst = kvout + ((size_t)bh * 128 + tid) * 32;
    #pragma unroll
    for (int m4 = 0; m4 < 8; m4++) {
        float4 v;
        v.x = acc[m4 * 4 + 0]; v.y = acc[m4 * 4 + 1];
        v.z = acc[m4 * 4 + 2]; v.w = acc[m4 * 4 + 3];
        *(float4*)(kvdst + m4 * 4) = v;
    }
    ksumout[(size_t)bh * 128 + tid] = kssum;
}

// ---------------- attention: attn[n][m] per (b,h) ----------------------------
__global__ void __launch_bounds__(256) attn_kernel(const float* __restrict__ q,
                                                   const float* __restrict__ kv,
                                                   const float* __restrict__ ksum,
                                                   float* __restrict__ attn)
{
    const int bh = blockIdx.y;                  // 512
    const int b = bh >> 3, hh = bh & 7;
    const int n0 = blockIdx.x * 64;             // 16 tiles
    const int tid = threadIdx.x;                // 256
    const int m = tid & 31, r = tid >> 5;       // r in 0..7

    __shared__ float q_sh[64][36];
    __shared__ float kvT[4][32][36];            // [t][m][j], stride 36 -> conflict-free
    __shared__ float ksum_sh[4][32];
    __shared__ float dp_sh[64][4];

    const float* qbase = q + ((size_t)(b * NN + n0)) * CC + hh * 32;
    #pragma unroll
    for (int p = 0; p < 2; p++) {
        int slot = p * 256 + tid;               // 0..511
        int nl = slot >> 3, jc = slot & 7;
        float4 v = *(const float4*)(qbase + (size_t)nl * CC + jc * 4);
        q_sh[nl][jc * 4 + 0] = v.x;
        q_sh[nl][jc * 4 + 1] = v.y;
        q_sh[nl][jc * 4 + 2] = v.z;
        q_sh[nl][jc * 4 + 3] = v.w;
    }
    const float* kvbase = kv + (size_t)bh * 128 * 32;
    #pragma unroll
    for (int p = 0; p < 4; p++) {
        int slot = p * 256 + tid;               // 0..1023
        int d = slot >> 3, mc = slot & 7;
        float4 v = *(const float4*)(kvbase + d * 32 + mc * 4);
        int t = d >> 5, j = d & 31;
        kvT[t][mc * 4 + 0][j] = v.x;
        kvT[t][mc * 4 + 1][j] = v.y;
        kvT[t][mc * 4 + 2][j] = v.z;
        kvT[t][mc * 4 + 3][j] = v.w;
    }
    if (tid < 128) ksum_sh[tid >> 5][tid & 31] = ksum[(size_t)bh * 128 + tid];
    __syncthreads();

    {   // denominator partials: dp[nl][t] = q[nl] . ksum_t
        int nl = tid >> 2, t = tid & 3;
        float s = 0.f;
        #pragma unroll
        for (int j = 0; j < 32; j++) s += q_sh[nl][j] * ksum_sh[t][j];
        dp_sh[nl][t] = s;
    }
    __syncthreads();

    float acc[8][4];
    #pragma unroll
    for (int s = 0; s < 8; s++)
        #pragma unroll
        for (int t = 0; t < 4; t++) acc[s][t] = 0.f;

    #pragma unroll
    for (int j4 = 0; j4 < 8; j4++) {
        float4 kq[4];
        #pragma unroll
        for (int t = 0; t < 4; t++) kq[t] = *(const float4*)&kvT[t][m][j4 * 4];
        #pragma unroll
        for (int s = 0; s < 8; s++) {
            int nl = r * 8 + s;
            float4 qv = *(const float4*)&q_sh[nl][j4 * 4];
            #pragma unroll
            for (int t = 0; t < 4; t++) {
                acc[s][t] += qv.x * kq[t].x + qv.y * kq[t].y
                           + qv.z * kq[t].z + qv.w * kq[t].w;
            }
        }
    }

    #pragma unroll
    for (int s = 0; s < 8; s++) {
        int nl = r * 8 + s;
        int n = n0 + nl;
        float sa, ca, sb, cb;
        sincosf((float)(n >> 5) * PI_OVER_64, &sa, &ca);
        sincosf((float)(n & 31) * PI_OVER_64, &sb, &cb);
        float den = ca * dp_sh[nl][0] + sa * dp_sh[nl][1]
                  + cb * dp_sh[nl][2] + sb * dp_sh[nl][3];
        float ad = fminf(fmaxf(fabsf(den), 1e-4f), 1e4f);
        den = (den < 0.f) ? -ad : ad;
        float num = ca * acc[s][0] + sa * acc[s][1]
                  + cb * acc[s][2] + sb * acc[s][3];
        attn[((size_t)(b * NN + n)) * CC + hh * 32 + m] = num / den;
    }
}

// ---------------- tf32 tensor-core GEMM: out = A(MxK) @ Bw(NxK)^T + bias -----
// AMODE: 0 plain row-major A
//        1 A is query read transposed: m=(b,n) -> query[n][b][k]
//        2 A is implicit conv patches from query: m=(b,ns), k=(dd,i)
// EMODE: 0 +bias; 1 +bias,relu; 2 (+bias)*QSCALE,relu; 3 out-proj (se mul + transposed store)
template<int AMODE>
__device__ __forceinline__ const float* a_index(const float* __restrict__ A, int m, int k, int K)
{
    if (AMODE == 0) {
        return A + (size_t)m * K + k;
    } else if (AMODE == 1) {
        return A + (size_t)(m & (NN - 1)) * (BB * CC) + (m >> 10) * CC + k;
    } else {
        int b = m >> 8, ns = m & 255;
        int dd = k >> 8, i = k & 255;
        int pos = (((ns >> 4) * 2 + (dd >> 1)) << 5) + ((ns & 15) * 2 + (dd & 1));
        return A + (size_t)pos * (BB * CC) + b * CC + i;
    }
}

// Block tile 128(M) x 128(N), BK=32. 8 warps: 4 along M x 2 along N.
// Warp tile 32x64: 2 m16-tiles x 8 n8-tiles of m16n8k8 tf32 mma.
template<int AMODE, int EMODE>
__global__ void __launch_bounds__(256, 2) mma_gemm_kernel(
    const float* __restrict__ A, const float* __restrict__ Bw,
    const float* __restrict__ bias, float* __restrict__ Cout,
    int M, int N, int K,
    const float* __restrict__ se, float* __restrict__ dout)
{
    __shared__ __align__(16) u32 As[128][36];   // [m][k], pitch 36 words
    __shared__ __align__(16) u32 Bs[128][36];   // [n][k]

    const int tid  = threadIdx.x;
    const int lane = tid & 31;
    const int wid  = tid >> 5;
    const int g = lane >> 2;        // groupID (row within fragment)
    const int t = lane & 3;         // threadID_in_group (col within fragment)
    const int wm = (wid & 3) * 32;  // warp M offset within CTA tile
    const int wn = (wid >> 2) * 64; // warp N offset within CTA tile
    const int m0 = blockIdx.x * 128;
    const int n0 = blockIdx.y * 128;

    float acc[2][8][4];
    #pragma unroll
    for (int mt = 0; mt < 2; mt++)
        #pragma unroll
        for (int nt = 0; nt < 8; nt++)
            #pragma unroll
            for (int c = 0; c < 4; c++) acc[mt][nt][c] = 0.f;

    for (int kt = 0; kt < K; kt += 32) {
        // Stage A tile (128x32) and B tile (128x32) as tf32 words.
        #pragma unroll
        for (int p = 0; p < 4; p++) {
            int slot = p * 256 + tid;          // 0..1023
            int mm = slot >> 3, kc = slot & 7; // row, k-quad
            float4 v = *(const float4*)a_index<AMODE>(A, m0 + mm, kt + kc * 4, K);
            uint4 w;
            w.x = f2tf32(v.x); w.y = f2tf32(v.y);
            w.z = f2tf32(v.z); w.w = f2tf32(v.w);
            *(uint4*)&As[mm][kc * 4] = w;
        }
        #pragma unroll
        for (int p = 0; p < 4; p++) {
            int slot = p * 256 + tid;
            int nn = slot >> 3, kc = slot & 7;
            float4 v = *(const float4*)(Bw + (size_t)(n0 + nn) * K + kt + kc * 4);
            uint4 w;
            w.x = f2tf32(v.x); w.y = f2tf32(v.y);
            w.z = f2tf32(v.z); w.w = f2tf32(v.w);
            *(uint4*)&Bs[nn][kc * 4] = w;
        }
        __syncthreads();

        #pragma unroll
        for (int kk = 0; kk < 32; kk += 8) {
            u32 afr[2][4], bfr[8][2];
            #pragma unroll
            for (int mt = 0; mt < 2; mt++) {
                int row = wm + mt * 16;
                afr[mt][0] = As[row + g][kk + t];
                afr[mt][1] = As[row + g + 8][kk + t];
                afr[mt][2] = As[row + g][kk + t + 4];
                afr[mt][3] = As[row + g + 8][kk + t + 4];
            }
            #pragma unroll
            for (int nt = 0; nt < 8; nt++) {
                int col = wn + nt * 8 + g;
                bfr[nt][0] = Bs[col][kk + t];
                bfr[nt][1] = Bs[col][kk + t + 4];
            }
            #pragma unroll
            for (int mt = 0; mt < 2; mt++)
                #pragma unroll
                for (int nt = 0; nt < 8; nt++)
                    mma_tf32(acc[mt][nt], afr[mt], bfr[nt]);
        }
        __syncthreads();
    }

    // Epilogue: thread owns rows {g, g+8} of each m16 tile, cols 2t,2t+1 of each n8 tile.
    #pragma unroll
    for (int mt = 0; mt < 2; mt++) {
        #pragma unroll
        for (int half = 0; half < 2; half++) {
            int mrow = m0 + wm + mt * 16 + g + half * 8;
            if (EMODE == 3) {
                int b = mrow >> 10, nseq = mrow & (NN - 1);
                float* drow = dout + ((size_t)nseq * BB + b) * CC;
                const float* serow = se + b * CC;
                #pragma unroll
                for (int nt = 0; nt < 8; nt++) {
                    int col = n0 + wn + nt * 8 + t * 2;
                    float2 o;
                    o.x = (acc[mt][nt][half * 2 + 0] + bias[col])     * serow[col];
                    o.y = (acc[mt][nt][half * 2 + 1] + bias[col + 1]) * serow[col + 1];
                    *(float2*)(drow + col) = o;
                }
            } else {
                float* crow = Cout + (size_t)mrow * N;
                #pragma unroll
                for (int nt = 0; nt < 8; nt++) {
                    int col = n0 + wn + nt * 8 + t * 2;
                    float v0 = acc[mt][nt][half * 2 + 0] + bias[col];
                    float v1 = acc[mt][nt][half * 2 + 1] + bias[col + 1];
                    if (EMODE == 1) { v0 = fmaxf(v0, 0.f); v1 = fmaxf(v1, 0.f); }
                    if (EMODE == 2) {
                        v0 = fmaxf(v0 * QSCALE, 0.f);
                        v1 = fmaxf(v1 * QSCALE, 0.f);
                    }
                    float2 o; o.x = v0; o.y = v1;
                    *(float2*)(crow + col) = o;
                }
            }
        }
    }
}

// ---------------- launch ------------------------------------------------------
extern "C" void kernel_launch(void* const* d_in, const int* in_sizes, int n_in,
                              void* d_out, int out_size)
{
    (void)in_sizes; (void)n_in; (void)out_size;
    const float* query = (const float*)d_in[0];
    // d_in[1]=H, d_in[2]=W (always 32), d_in[3]=key, d_in[4]=value : unused
    const float* ipw  = (const float*)d_in[5];
    const float* ipb  = (const float*)d_in[6];
    const float* srw  = (const float*)d_in[7];
    const float* srb  = (const float*)d_in[8];
    const float* ng   = (const float*)d_in[9];
    const float* nb   = (const float*)d_in[10];
    const float* outw = (const float*)d_in[11];
    const float* outb = (const float*)d_in[12];
    const float* sew1 = (const float*)d_in[13];
    const float* sew2 = (const float*)d_in[14];
    float* out = (float*)d_out;

    float *xr, *qb, *kb, *vb, *kv, *ks, *attn, *wt, *se, *sein;
    cudaGetSymbolAddress((void**)&xr,   g_xr);
    cudaGetSymbolAddress((void**)&qb,   g_q);
    cudaGetSymbolAddress((void**)&kb,   g_kb);
    cudaGetSymbolAddress((void**)&vb,   g_vb);
    cudaGetSymbolAddress((void**)&kv,   g_kv);
    cudaGetSymbolAddress((void**)&ks,   g_ksum);
    cudaGetSymbolAddress((void**)&attn, g_attn);
    cudaGetSymbolAddress((void**)&wt,   g_wt);
    cudaGetSymbolAddress((void**)&se,   g_se);
    cudaGetSymbolAddress((void**)&sein, g_sein);

    // SE path
    se_mean_kernel<<<64, 256>>>(query, sein);
    se_mlp_kernel<<<64, 256>>>(sein, sew1, sew2, se);

    // conv (as GEMM over implicit patches) + bias, then layernorm (in-place)
    wtrans_kernel<<<1024, 256>>>(srw, wt);
    mma_gemm_kernel<2, 0><<<dim3(128, 2), 256>>>(query, wt, srb, xr,
                                                 BB * NS, CC, 1024, nullptr, nullptr);
    ln_kernel<<<2048, 256>>>(xr, ng, nb);

    // projections
    mma_gemm_kernel<1, 2><<<dim3(512, 2), 256>>>(query, ipw, ipb, qb,
                                                 BB * NN, CC, CC, nullptr, nullptr);
    mma_gemm_kernel<0, 1><<<dim3(128, 2), 256>>>(xr, ipw + CC * CC, ipb + CC, kb,
                                                 BB * NS, CC, CC, nullptr, nullptr);
    mma_gemm_kernel<0, 0><<<dim3(128, 2), 256>>>(xr, ipw + 2 * CC * CC, ipb + 2 * CC, vb,
                                                 BB * NS, CC, CC, nullptr, nullptr);

    // cosformer linear attention
    kv_kernel<<<512, 128>>>(kb, vb, kv, ks);
    attn_kernel<<<dim3(16, 512), 256>>>(qb, kv, ks, attn);

    // output projection + SE gating + transpose to (N,B,C)
    mma_gemm_kernel<0, 3><<<dim3(512, 2), 256>>>(attn, outw, outb, nullptr,
                                                 BB * NN, CC, CC, se, out);
}

// round 4
// speedup vs baseline: 2.0255x; 1.1791x over previous
#include <cuda_runtime.h>
#include <cuda_bf16.h>
#include <math.h>
#include <cstdint>

// Problem constants (fixed by setup_inputs): N=1024, B=64, C=256, h=8, hd=32,
// H=W=32, SR=2 -> Hs=Ws=16, Ns=256.
#define NN 1024
#define BB 64
#define CC 256
#define NHEAD 8
#define HD 32
#define NS 256
#define PI_OVER_64 0.04908738521234052f   // (pi/2)/32
#define PI_OVER_32 0.09817477042468103f   // (pi/2)/16
#define QSCALE 0.17677669529663687f       // 32^-0.5

typedef unsigned int u32;

// ---------------- device scratch (allocation-free: module-load static) -------
__device__ float g_xr[BB * NS * CC];          // conv output -> layernormed (tf32-rounded)
__device__ float g_q[BB * NN * CC];           // q projection, relu'd, tf32-rounded
__device__ float g_kb[BB * NS * CC];          // k projection, relu'd
__device__ float g_vb[BB * NS * CC];          // v projection
__device__ float g_kv[BB * NHEAD * 128 * 32]; // per (b,h): kv[d=t*32+j][m], tf32-rounded
__device__ float g_ksum[BB * NHEAD * 128];    // per (b,h): ksum[d]
__device__ float g_attn[BB * NN * CC];        // attention output, tf32-rounded
__device__ float g_wt[CC * 1024];             // conv weights permuted (O, dd, I), tf32
__device__ float g_se[BB * CC];               // SE gate
__device__ float g_sein[BB * CC];             // mean over N
__device__ float g_qtf[NN * BB * CC];         // query, tf32-rounded (same layout)
__device__ float g_ipwtf[3 * CC * CC];        // in_proj_weight, tf32-rounded
__device__ float g_outwtf[CC * CC];           // out_w, tf32-rounded
__device__ float g_angN[NN * 4];              // per n: cos_a, sin_a, cos_b, sin_b
__device__ float g_angS[NS * 4];              // per s (downsampled)

// ---------------- helpers -----------------------------------------------------
__device__ __forceinline__ u32 f2tf32(float x)
{
    u32 r;
    asm("cvt.rna.tf32.f32 %0, %1;" : "=r"(r) : "f"(x));
    return r;
}
__device__ __forceinline__ float tf32r(float x) { return __uint_as_float(f2tf32(x)); }

__device__ __forceinline__ void mma_tf32(float* c, const u32* a, const u32* b)
{
    asm volatile(
        "mma.sync.aligned.m16n8k8.row.col.f32.tf32.tf32.f32 "
        "{%0,%1,%2,%3}, {%4,%5,%6,%7}, {%8,%9}, {%0,%1,%2,%3};"
        : "+f"(c[0]), "+f"(c[1]), "+f"(c[2]), "+f"(c[3])
        : "r"(a[0]), "r"(a[1]), "r"(a[2]), "r"(a[3]),
          "r"(b[0]), "r"(b[1]));
}

__device__ __forceinline__ u32 smem_u32(const void* p)
{
    u32 a;
    asm("{ .reg .u64 t; cvta.to.shared.u64 t, %1; cvt.u32.u64 %0, t; }"
        : "=r"(a) : "l"(p));
    return a;
}

#define CP_ASYNC16(dst, src) \
    asm volatile("cp.async.cg.shared.global [%0], [%1], 16;" :: "r"(dst), "l"(src))
#define CP_COMMIT() asm volatile("cp.async.commit_group;")
#define CP_WAIT1()  asm volatile("cp.async.wait_group 1;")
#define CP_WAIT0()  asm volatile("cp.async.wait_group 0;")

// ---------------- small kernels ----------------------------------------------
__global__ void cvt_kernel(const float* __restrict__ src, float* __restrict__ dst)
{
    int i = blockIdx.x * 256 + threadIdx.x;
    dst[i] = tf32r(src[i]);
}

__global__ void wtrans_kernel(const float* __restrict__ srw, float* __restrict__ wt)
{
    int idx = blockIdx.x * 256 + threadIdx.x;   // 256*1024 elems, grid 1024
    int o = idx >> 10, rest = idx & 1023;
    int dd = rest >> 8, i = rest & 255;
    wt[idx] = tf32r(srw[(o << 10) + (i << 2) + dd]);
}

__global__ void ang_kernel(float* __restrict__ angN, float* __restrict__ angS)
{
    int n = blockIdx.x * 256 + threadIdx.x;     // grid 4 -> 1024
    {
        float a = (float)(n >> 5) * PI_OVER_64;
        float b = (float)(n & 31) * PI_OVER_64;
        float sa, ca, sb, cb;
        sincosf(a, &sa, &ca);
        sincosf(b, &sb, &cb);
        float4 w; w.x = ca; w.y = sa; w.z = cb; w.w = sb;
        *(float4*)(angN + n * 4) = w;
    }
    if (n < NS) {
        float a = (float)(n >> 4) * PI_OVER_32;
        float b = (float)(n & 15) * PI_OVER_32;
        float sa, ca, sb, cb;
        sincosf(a, &sa, &ca);
        sincosf(b, &sb, &cb);
        float4 w; w.x = ca; w.y = sa; w.z = cb; w.w = sb;
        *(float4*)(angS + n * 4) = w;
    }
}

__global__ void se_mean_kernel(const float* __restrict__ query, float* __restrict__ sein)
{
    int idx = blockIdx.x * 256 + threadIdx.x;   // 16384 (b*C+c), grid 64
    float s = 0.f;
    #pragma unroll 8
    for (int n = 0; n < NN; n++) s += query[(size_t)n * (BB * CC) + idx];
    sein[idx] = s * (1.0f / (float)NN);
}

__global__ void se_mlp_kernel(const float* __restrict__ sein,
                              const float* __restrict__ w1,
                              const float* __restrict__ w2,
                              float* __restrict__ se)
{
    int b = blockIdx.x;
    int tid = threadIdx.x;                       // 256
    __shared__ float xin[256];
    __shared__ float hid[128];
    xin[tid] = sein[b * 256 + tid];
    __syncthreads();
    if (tid < 128) {
        float s = 0.f;
        #pragma unroll 8
        for (int c = 0; c < 256; c++) s += xin[c] * w1[tid * 256 + c];
        hid[tid] = fmaxf(s, 0.f);
    }
    __syncthreads();
    float s = 0.f;
    #pragma unroll 8
    for (int r = 0; r < 128; r++) s += hid[r] * w2[tid * 128 + r];
    se[b * 256 + tid] = 1.f / (1.f + expf(-s));
}

__global__ void ln_kernel(float* __restrict__ x,
                          const float* __restrict__ gg,
                          const float* __restrict__ bb)
{
    int row = blockIdx.x * 8 + (threadIdx.x >> 5);   // 16384 rows of 256
    int lane = threadIdx.x & 31;
    float* xr = x + (size_t)row * 256;
    float4 v0 = ((float4*)xr)[lane];
    float4 v1 = ((float4*)xr)[32 + lane];
    float s  = v0.x + v0.y + v0.z + v0.w + v1.x + v1.y + v1.z + v1.w;
    float sq = v0.x*v0.x + v0.y*v0.y + v0.z*v0.z + v0.w*v0.w
             + v1.x*v1.x + v1.y*v1.y + v1.z*v1.z + v1.w*v1.w;
    #pragma unroll
    for (int o = 16; o > 0; o >>= 1) {
        s  += __shfl_xor_sync(0xffffffffu, s,  o);
        sq += __shfl_xor_sync(0xffffffffu, sq, o);
    }
    float mean = s * (1.f / 256.f);
    float var  = sq * (1.f / 256.f) - mean * mean;
    float rstd = rsqrtf(var + 1e-5f);
    const float4 gA = ((const float4*)gg)[lane];
    const float4 gB = ((const float4*)gg)[32 + lane];
    const float4 bA = ((const float4*)bb)[lane];
    const float4 bB = ((const float4*)bb)[32 + lane];
    float4 r0, r1;
    r0.x = tf32r((v0.x - mean) * rstd * gA.x + bA.x);
    r0.y = tf32r((v0.y - mean) * rstd * gA.y + bA.y);
    r0.z = tf32r((v0.z - mean) * rstd * gA.z + bA.z);
    r0.w = tf32r((v0.w - mean) * rstd * gA.w + bA.w);
    r1.x = tf32r((v1.x - mean) * rstd * gB.x + bB.x);
    r1.y = tf32r((v1.y - mean) * rstd * gB.y + bB.y);
    r1.z = tf32r((v1.z - mean) * rstd * gB.z + bB.z);
    r1.w = tf32r((v1.w - mean) * rstd * gB.w + bB.w);
    ((float4*)xr)[lane] = r0;
    ((float4*)xr)[32 + lane] = r1;
}

// ---------------- kv aggregation: kv[t*32+j][m], ksum[t*32+j] ----------------
__global__ void __launch_bounds__(128) kv_kernel(const float* __restrict__ kbuf,
                                                 const float* __restrict__ vbuf,
                                                 const float* __restrict__ angS,
                                                 float* __restrict__ kvout,
                                                 float* __restrict__ ksumout)
{
    const int bh = blockIdx.x;                 // 512
    const int b = bh >> 3, hh = bh & 7;
    const int tid = threadIdx.x;               // 128
    const int t = tid >> 5, j = tid & 31;
    __shared__ float ksh[8][32];
    __shared__ float vsh[8][32];
    __shared__ float wsh[8][4];
    float acc[32];
    #pragma unroll
    for (int m = 0; m < 32; m++) acc[m] = 0.f;
    float kssum = 0.f;
    const float* kbase = kbuf + (size_t)b * NS * CC + hh * 32;
    const float* vbase = vbuf + (size_t)b * NS * CC + hh * 32;

    for (int s0 = 0; s0 < NS; s0 += 8) {
        {
            int idx = tid & 63, sr = idx >> 3, c4 = idx & 7;
            const float* src = (tid < 64 ? kbase : vbase) + (size_t)(s0 + sr) * CC + c4 * 4;
            float4 v = *(const float4*)src;
            float* dst = (tid < 64) ? &ksh[sr][c4 * 4] : &vsh[sr][c4 * 4];
            dst[0] = v.x; dst[1] = v.y; dst[2] = v.z; dst[3] = v.w;
        }
        if (tid < 32) {
            int sr2 = tid >> 2, tt = tid & 3;
            wsh[sr2][tt] = angS[(s0 + sr2) * 4 + tt];
        }
        __syncthreads();
        #pragma unroll
        for (int sr2 = 0; sr2 < 8; sr2++) {
            float kw = ksh[sr2][j] * wsh[sr2][t];
            kssum += kw;
            #pragma unroll
            for (int m4 = 0; m4 < 8; m4++) {
                float4 vv = *(const float4*)&vsh[sr2][m4 * 4];
                acc[m4 * 4 + 0] += kw * vv.x;
                acc[m4 * 4 + 1] += kw * vv.y;
                acc[m4 * 4 + 2] += kw * vv.z;
                acc[m4 * 4 + 3] += kw * vv.w;
            }
        }
        __syncthreads();
    }
    float* kvdst = kvout + ((size_t)bh * 128 + tid) * 32;
    #pragma unroll
    for (int m4 = 0; m4 < 8; m4++) {
        float4 v;
        v.x = tf32r(acc[m4 * 4 + 0]); v.y = tf32r(acc[m4 * 4 + 1]);
        v.z = tf32r(acc[m4 * 4 + 2]); v.w = tf32r(acc[m4 * 4 + 3]);
        *(float4*)(kvdst + m4 * 4) = v;
    }
    ksumout[(size_t)bh * 128 + tid] = kssum;
}

// ---------------- attention via tensor cores ----------------------------------
// Per (b,h) and 128-row n-tile: S_t = q @ kv_t^T (4 GEMMs, K=32, shared A),
// num = sum_t w_t(n) * S_t, den = sum_t w_t(n) * (q . ksum_t).
__global__ void __launch_bounds__(256, 2) attn_mma_kernel(
    const float* __restrict__ q, const float* __restrict__ kv,
    const float* __restrict__ ksum, const float* __restrict__ angN,
    float* __restrict__ attn)
{
    const int bh = blockIdx.y;                  // 512
    const int b = bh >> 3, hh = bh & 7;
    const int n0 = blockIdx.x * 128;            // 8 tiles
    const int tid  = threadIdx.x;
    const int lane = tid & 31;
    const int wid  = tid >> 5;                  // 0..7
    const int g = lane >> 2, t = lane & 3;
    const int wm = wid * 16;

    __shared__ __align__(16) u32 q_sh[128][36];   // [n][j] tf32 bits
    __shared__ u32 B_sh[4][32][36];               // [t][m][j] tf32 bits (kv transposed)
    __shared__ float ksum_sh[4][32];
    __shared__ float dp_sh[128][4];

    const float* qbase = q + ((size_t)(b * NN + n0)) * CC + hh * 32;
    #pragma unroll
    for (int p = 0; p < 4; p++) {
        int slot = p * 256 + tid;               // 0..1023
        int nl = slot >> 3, jc = slot & 7;
        float4 v = *(const float4*)(qbase + (size_t)nl * CC + jc * 4);
        q_sh[nl][jc * 4 + 0] = __float_as_uint(v.x);
        q_sh[nl][jc * 4 + 1] = __float_as_uint(v.y);
        q_sh[nl][jc * 4 + 2] = __float_as_uint(v.z);
        q_sh[nl][jc * 4 + 3] = __float_as_uint(v.w);
    }
    const float* kvbase = kv + (size_t)bh * 128 * 32;
    #pragma unroll
    for (int p = 0; p < 4; p++) {
        int slot = p * 256 + tid;               // 0..1023
        int d = slot >> 3, mc = slot & 7;       // d = t*32+j
        float4 v = *(const float4*)(kvbase + d * 32 + mc * 4);
        int tt = d >> 5, j = d & 31;
        B_sh[tt][mc * 4 + 0][j] = __float_as_uint(v.x);
        B_sh[tt][mc * 4 + 1][j] = __float_as_uint(v.y);
        B_sh[tt][mc * 4 + 2][j] = __float_as_uint(v.z);
        B_sh[tt][mc * 4 + 3][j] = __float_as_uint(v.w);
    }
    if (tid < 128) ksum_sh[tid >> 5][tid & 31] = ksum[(size_t)bh * 128 + tid];
    __syncthreads();

    // denominator partials: dp[nl][t] = q[nl] . ksum_t  (512 entries, 2/thread)
    #pragma unroll
    for (int e = 0; e < 2; e++) {
        int idx = e * 256 + tid;
        int nl = idx >> 2, tt = idx & 3;
        float s = 0.f;
        #pragma unroll
        for (int j = 0; j < 32; j++)
            s += __uint_as_float(q_sh[nl][j]) * ksum_sh[tt][j];
        dp_sh[nl][tt] = s;
    }
    __syncthreads();

    float acc[4][4][4];                          // [t][nt][c]
    #pragma unroll
    for (int tt = 0; tt < 4; tt++)
        #pragma unroll
        for (int nt = 0; nt < 4; nt++)
            #pragma unroll
            for (int c = 0; c < 4; c++) acc[tt][nt][c] = 0.f;

    #pragma unroll
    for (int kk8 = 0; kk8 < 4; kk8++) {
        int kkk = kk8 * 8;
        u32 afr[4];
        afr[0] = q_sh[wm + g][kkk + t];
        afr[1] = q_sh[wm + g + 8][kkk + t];
        afr[2] = q_sh[wm + g][kkk + t + 4];
        afr[3] = q_sh[wm + g + 8][kkk + t + 4];
        #pragma unroll
        for (int tt = 0; tt < 4; tt++) {
            #pragma unroll
            for (int nt = 0; nt < 4; nt++) {
                u32 bfr[2];
                bfr[0] = B_sh[tt][nt * 8 + g][kkk + t];
                bfr[1] = B_sh[tt][nt * 8 + g][kkk + t + 4];
                mma_tf32(acc[tt][nt], afr, bfr);
            }
        }
    }

    #pragma unroll
    for (int half = 0; half < 2; half++) {
        int nl = wm + g + half * 8;
        int n = n0 + nl;
        float4 w = *(const float4*)(angN + n * 4);
        float den = w.x * dp_sh[nl][0] + w.y * dp_sh[nl][1]
                  + w.z * dp_sh[nl][2] + w.w * dp_sh[nl][3];
        float ad = fminf(fmaxf(fabsf(den), 1e-4f), 1e4f);
        den = (den < 0.f) ? -ad : ad;
        float rden = 1.f / den;
        float* arow = attn + ((size_t)(b * NN + n)) * CC + hh * 32;
        #pragma unroll
        for (int nt = 0; nt < 4; nt++) {
            #pragma unroll
            for (int c2 = 0; c2 < 2; c2++) {
                int ci = half * 2 + c2;
                int col = nt * 8 + t * 2 + c2;
                float num = w.x * acc[0][nt][ci] + w.y * acc[1][nt][ci]
                          + w.z * acc[2][nt][ci] + w.w * acc[3][nt][ci];
                arow[col] = tf32r(num * rden);
            }
        }
    }
}

// ---------------- tf32 tensor-core GEMM with cp.async double buffering -------
// Inputs A, Bw MUST already hold tf32-rounded bit patterns.
// AMODE: 0 plain row-major A; 1 query transposed; 2 implicit conv patches.
// EMODE: 0 +bias; 2 (+bias)*QSCALE,relu,round; 3 out-proj (se + transposed store);
//        4 fused k/v: col<256 -> relu -> Cout(kb), else -> dout(vb).
template<int AMODE>
__device__ __forceinline__ const float* a_index(const float* __restrict__ A, int m, int k, int K)
{
    if (AMODE == 0) {
        return A + (size_t)m * K + k;
    } else if (AMODE == 1) {
        return A + (size_t)(m & (NN - 1)) * (BB * CC) + (m >> 10) * CC + k;
    } else {
        int b = m >> 8, ns = m & 255;
        int dd = k >> 8, i = k & 255;
        int pos = (((ns >> 4) * 2 + (dd >> 1)) << 5) + ((ns & 15) * 2 + (dd & 1));
        return A + (size_t)pos * (BB * CC) + b * CC + i;
    }
}

template<int AMODE, int EMODE>
__global__ void __launch_bounds__(256, 2) mma_gemm_kernel(
    const float* __restrict__ A, const float* __restrict__ Bw,
    const float* __restrict__ bias, float* __restrict__ Cout,
    int M, int N, int K,
    const float* __restrict__ se, float* __restrict__ dout)
{
    __shared__ __align__(16) u32 As[2 * 128][20];   // 2 stages, BK=16, pitch 20
    __shared__ __align__(16) u32 Bs[2 * 128][20];

    const int tid  = threadIdx.x;
    const int lane = tid & 31;
    const int wid  = tid >> 5;
    const int g = lane >> 2;
    const int t = lane & 3;
    const int wm = (wid & 3) * 32;
    const int wn = (wid >> 2) * 64;
    const int m0 = blockIdx.x * 128;
    const int n0 = blockIdx.y * 128;

    const u32 sA = smem_u32(&As[0][0]);
    const u32 sB = smem_u32(&Bs[0][0]);

    float acc[2][8][4];
    #pragma unroll
    for (int mt = 0; mt < 2; mt++)
        #pragma unroll
        for (int nt = 0; nt < 8; nt++)
            #pragma unroll
            for (int c = 0; c < 4; c++) acc[mt][nt][c] = 0.f;

    const int nkt = K >> 4;

    // --- issue helper (inline twice + loop) ---
    #define ISSUE_STAGE(stage, kt)                                              \
        do {                                                                     \
            _Pragma("unroll")                                                    \
            for (int p = 0; p < 2; p++) {                                        \
                int cch = p * 256 + tid;                                         \
                int row = cch >> 2, kc = cch & 3;                                \
                const float* srcA = a_index<AMODE>(A, m0 + row, (kt) + kc * 4, K); \
                u32 dA = sA + (((stage) * 128 + row) * 20 + kc * 4) * 4;         \
                CP_ASYNC16(dA, srcA);                                            \
                const float* srcB = Bw + (size_t)(n0 + row) * K + (kt) + kc * 4; \
                u32 dB = sB + (((stage) * 128 + row) * 20 + kc * 4) * 4;         \
                CP_ASYNC16(dB, srcB);                                            \
            }                                                                    \
            CP_COMMIT();                                                         \
        } while (0)

    ISSUE_STAGE(0, 0);
    ISSUE_STAGE(1, 16);

    for (int i = 0; i < nkt; i++) {
        CP_WAIT1();
        __syncthreads();
        const int buf = i & 1;
        const int base = buf * 128;
        #pragma unroll
        for (int kk = 0; kk < 16; kk += 8) {
            u32 afr[2][4], bfr[8][2];
            #pragma unroll
            for (int mt = 0; mt < 2; mt++) {
                int row = base + wm + mt * 16;
                afr[mt][0] = As[row + g][kk + t];
                afr[mt][1] = As[row + g + 8][kk + t];
                afr[mt][2] = As[row + g][kk + t + 4];
                afr[mt][3] = As[row + g + 8][kk + t + 4];
            }
            #pragma unroll
            for (int nt = 0; nt < 8; nt++) {
                int col = base + wn + nt * 8 + g;
                bfr[nt][0] = Bs[col][kk + t];
                bfr[nt][1] = Bs[col][kk + t + 4];
            }
            #pragma unroll
            for (int mt = 0; mt < 2; mt++)
                #pragma unroll
                for (int nt = 0; nt < 8; nt++)
                    mma_tf32(acc[mt][nt], afr[mt], bfr[nt]);
        }
        __syncthreads();
        int nx = i + 2;
        if (nx < nkt) {
            ISSUE_STAGE(buf, nx * 16);
        } else {
            CP_COMMIT();   // empty group keeps wait_group accounting in order
        }
    }
    CP_WAIT0();
    #undef ISSUE_STAGE

    // Epilogue: thread owns rows {g, g+8} of each m16 tile, cols 2t,2t+1 of each n8 tile.
    #pragma unroll
    for (int mt = 0; mt < 2; mt++) {
        #pragma unroll
        for (int half = 0; half < 2; half++) {
            int mrow = m0 + wm + mt * 16 + g + half * 8;
            if (EMODE == 3) {
                int b = mrow >> 10, nseq = mrow & (NN - 1);
                float* drow = dout + ((size_t)nseq * BB + b) * CC;
                const float* serow = se + b * CC;
                #pragma unroll
                for (int nt = 0; nt < 8; nt++) {
                    int col = n0 + wn + nt * 8 + t * 2;
                    float2 o;
                    o.x = (acc[mt][nt][half * 2 + 0] + bias[col])     * serow[col];
                    o.y = (acc[mt][nt][half * 2 + 1] + bias[col + 1]) * serow[col + 1];
                    *(float2*)(drow + col) = o;
                }
            } else if (EMODE == 4) {
                #pragma unroll
                for (int nt = 0; nt < 8; nt++) {
                    int col = n0 + wn + nt * 8 + t * 2;
                    float v0 = acc[mt][nt][half * 2 + 0] + bias[col];
                    float v1 = acc[mt][nt][half * 2 + 1] + bias[col + 1];
                    float2 o;
                    if (col < 256) {
                        o.x = fmaxf(v0, 0.f); o.y = fmaxf(v1, 0.f);
                        *(float2*)(Cout + (size_t)mrow * 256 + col) = o;
                    } else {
                        o.x = v0; o.y = v1;
                        *(float2*)(dout + (size_t)mrow * 256 + col - 256) = o;
                    }
                }
            } else {
                float* crow = Cout + (size_t)mrow * N;
                #pragma unroll
                for (int nt = 0; nt < 8; nt++) {
                    int col = n0 + wn + nt * 8 + t * 2;
                    float v0 = acc[mt][nt][half * 2 + 0] + bias[col];
                    float v1 = acc[mt][nt][half * 2 + 1] + bias[col + 1];
                    if (EMODE == 2) {
                        v0 = tf32r(fmaxf(v0 * QSCALE, 0.f));
                        v1 = tf32r(fmaxf(v1 * QSCALE, 0.f));
                    }
                    float2 o; o.x = v0; o.y = v1;
                    *(float2*)(crow + col) = o;
                }
            }
        }
    }
}

// ---------------- launch ------------------------------------------------------
extern "C" void kernel_launch(void* const* d_in, const int* in_sizes, int n_in,
                              void* d_out, int out_size)
{
    (void)in_sizes; (void)n_in; (void)out_size;
    const float* query = (const float*)d_in[0];
    // d_in[1]=H, d_in[2]=W (always 32), d_in[3]=key, d_in[4]=value : unused
    const float* ipw  = (const float*)d_in[5];
    const float* ipb  = (const float*)d_in[6];
    const float* srw  = (const float*)d_in[7];
    const float* srb  = (const float*)d_in[8];
    const float* ng   = (const float*)d_in[9];
    const float* nb   = (const float*)d_in[10];
    const float* outw = (const float*)d_in[11];
    const float* outb = (const float*)d_in[12];
    const float* sew1 = (const float*)d_in[13];
    const float* sew2 = (const float*)d_in[14];
    float* out = (float*)d_out;

    float *xr, *qb, *kb, *vb, *kv, *ks, *attn, *wt, *se, *sein;
    float *qtf, *ipwtf, *outwtf, *angN, *angS;
    cudaGetSymbolAddress((void**)&xr,     g_xr);
    cudaGetSymbolAddress((void**)&qb,     g_q);
    cudaGetSymbolAddress((void**)&kb,     g_kb);
    cudaGetSymbolAddress((void**)&vb,     g_vb);
    cudaGetSymbolAddress((void**)&kv,     g_kv);
    cudaGetSymbolAddress((void**)&ks,     g_ksum);
    cudaGetSymbolAddress((void**)&attn,   g_attn);
    cudaGetSymbolAddress((void**)&wt,     g_wt);
    cudaGetSymbolAddress((void**)&se,     g_se);
    cudaGetSymbolAddress((void**)&sein,   g_sein);
    cudaGetSymbolAddress((void**)&qtf,    g_qtf);
    cudaGetSymbolAddress((void**)&ipwtf,  g_ipwtf);
    cudaGetSymbolAddress((void**)&outwtf, g_outwtf);
    cudaGetSymbolAddress((void**)&angN,   g_angN);
    cudaGetSymbolAddress((void**)&angS,   g_angS);

    // pre-passes: tf32 conversions, weight transpose, angle tables, SE mean
    cvt_kernel<<<65536, 256>>>(query, qtf);
    cvt_kernel<<<768, 256>>>(ipw, ipwtf);
    cvt_kernel<<<256, 256>>>(outw, outwtf);
    wtrans_kernel<<<1024, 256>>>(srw, wt);
    ang_kernel<<<4, 256>>>(angN, angS);
    se_mean_kernel<<<64, 256>>>(query, sein);
    se_mlp_kernel<<<64, 256>>>(sein, sew1, sew2, se);

    // conv (as GEMM over implicit patches) + bias, then layernorm (in-place, rounds)
    mma_gemm_kernel<2, 0><<<dim3(128, 2), 256>>>(qtf, wt, srb, xr,
                                                 BB * NS, CC, 1024, nullptr, nullptr);
    ln_kernel<<<2048, 256>>>(xr, ng, nb);

    // projections
    mma_gemm_kernel<1, 2><<<dim3(512, 2), 256>>>(qtf, ipwtf, ipb, qb,
                                                 BB * NN, CC, CC, nullptr, nullptr);
    mma_gemm_kernel<0, 4><<<dim3(128, 4), 256>>>(xr, ipwtf + CC * CC, ipb + CC, kb,
                                                 BB * NS, 512, CC, nullptr, vb);

    // cosformer linear attention
    kv_kernel<<<512, 128>>>(kb, vb, angS, kv, ks);
    attn_mma_kernel<<<dim3(8, 512), 256>>>(qb, kv, ks, angN, attn);

    // output projection + SE gating + transpose to (N,B,C)
    mma_gemm_kernel<0, 3><<<dim3(512, 2), 256>>>(attn, outwtf, outb, nullptr,
                                                 BB * NN, CC, CC, se, out);
}

// round 5
// speedup vs baseline: 2.6207x; 1.2938x over previous
#include <cuda_runtime.h>
#include <cuda_bf16.h>
#include <math.h>
#include <cstdint>

// Problem constants (fixed by setup_inputs): N=1024, B=64, C=256, h=8, hd=32,
// H=W=32, SR=2 -> Hs=Ws=16, Ns=256.
#define NN 1024
#define BB 64
#define CC 256
#define NHEAD 8
#define HD 32
#define NS 256
#define PI_OVER_64 0.04908738521234052f   // (pi/2)/32
#define PI_OVER_32 0.09817477042468103f   // (pi/2)/16
#define QSCALE 0.17677669529663687f       // 32^-0.5

typedef unsigned int u32;

// ---------------- device scratch (allocation-free: module-load static) -------
__device__ float g_xr[BB * NS * CC];          // conv output -> layernormed (tf32-rounded)
__device__ float g_q[BB * NN * CC];           // q projection, relu'd, tf32-rounded
__device__ float g_kb[BB * NS * CC];          // k projection, relu'd
__device__ float g_vb[BB * NS * CC];          // v projection
__device__ float g_kv[BB * NHEAD * 128 * 32]; // per (b,h): kv[d=t*32+j][m], tf32-rounded
__device__ float g_ksum[BB * NHEAD * 128];    // per (b,h): ksum[d]
__device__ float g_attn[BB * NN * CC];        // attention output, tf32-rounded
__device__ float g_wt[CC * 1024];             // conv weights permuted (O, dd, I), tf32
__device__ float g_se[BB * CC];               // SE gate
__device__ float g_sein[4 * BB * CC];         // partial sums over n-chunks
__device__ float g_qtf[NN * BB * CC];         // query, tf32-rounded (same layout)
__device__ float g_ipwtf[3 * CC * CC];        // in_proj_weight, tf32-rounded
__device__ float g_outwtf[CC * CC];           // out_w, tf32-rounded
__device__ float g_angN[NN * 4];              // per n: cos_a, sin_a, cos_b, sin_b
__device__ float g_angS[NS * 4];              // per s (downsampled)

// ---------------- helpers -----------------------------------------------------
__device__ __forceinline__ u32 f2tf32(float x)
{
    u32 r;
    asm("cvt.rna.tf32.f32 %0, %1;" : "=r"(r) : "f"(x));
    return r;
}
__device__ __forceinline__ float tf32r(float x) { return __uint_as_float(f2tf32(x)); }

__device__ __forceinline__ void mma_tf32(float* c, const u32* a, const u32* b)
{
    asm volatile(
        "mma.sync.aligned.m16n8k8.row.col.f32.tf32.tf32.f32 "
        "{%0,%1,%2,%3}, {%4,%5,%6,%7}, {%8,%9}, {%0,%1,%2,%3};"
        : "+f"(c[0]), "+f"(c[1]), "+f"(c[2]), "+f"(c[3])
        : "r"(a[0]), "r"(a[1]), "r"(a[2]), "r"(a[3]),
          "r"(b[0]), "r"(b[1]));
}

__device__ __forceinline__ u32 smem_u32(const void* p)
{
    u32 a;
    asm("{ .reg .u64 t; cvta.to.shared.u64 t, %1; cvt.u32.u64 %0, t; }"
        : "=r"(a) : "l"(p));
    return a;
}

#define CP_ASYNC16(dst, src) \
    asm volatile("cp.async.cg.shared.global [%0], [%1], 16;" :: "r"(dst), "l"(src))
#define CP_COMMIT() asm volatile("cp.async.commit_group;")
#define CP_WAIT2()  asm volatile("cp.async.wait_group 2;")
#define CP_WAIT0()  asm volatile("cp.async.wait_group 0;")

// ---------------- fused prep: ipw cvt | outw cvt | wtrans | angles -----------
__global__ void prep_kernel(const float* __restrict__ ipw,
                            const float* __restrict__ outw,
                            const float* __restrict__ srw,
                            float* __restrict__ ipwtf,
                            float* __restrict__ outwtf,
                            float* __restrict__ wt,
                            float* __restrict__ angN,
                            float* __restrict__ angS)
{
    int bid = blockIdx.x;
    int tid = threadIdx.x;
    if (bid < 768) {                             // ipw: 196608 elems
        int i = bid * 256 + tid;
        ipwtf[i] = tf32r(ipw[i]);
    } else if (bid < 1024) {                     // outw: 65536
        int i = (bid - 768) * 256 + tid;
        outwtf[i] = tf32r(outw[i]);
    } else if (bid < 2048) {                     // wtrans: 262144
        int idx = (bid - 1024) * 256 + tid;
        int o = idx >> 10, rest = idx & 1023;
        int dd = rest >> 8, i = rest & 255;
        wt[idx] = tf32r(srw[(o << 10) + (i << 2) + dd]);
    } else {                                     // angles: 1024
        int n = (bid - 2048) * 256 + tid;
        {
            float a = (float)(n >> 5) * PI_OVER_64;
            float b = (float)(n & 31) * PI_OVER_64;
            float sa, ca, sb, cb;
            sincosf(a, &sa, &ca);
            sincosf(b, &sb, &cb);
            float4 w; w.x = ca; w.y = sa; w.z = cb; w.w = sb;
            *(float4*)(angN + n * 4) = w;
        }
        if (n < NS) {
            float a = (float)(n >> 4) * PI_OVER_32;
            float b = (float)(n & 15) * PI_OVER_32;
            float sa, ca, sb, cb;
            sincosf(a, &sa, &ca);
            sincosf(b, &sb, &cb);
            float4 w; w.x = ca; w.y = sa; w.z = cb; w.w = sb;
            *(float4*)(angS + n * 4) = w;
        }
    }
}

// ---------------- fused query tf32-round + column partial mean ---------------
// grid 256: blockIdx = chunk*64 + colblk; thread column idx = colblk*256+tid,
// n range [chunk*256, chunk*256+256).
__global__ void cvtq_kernel(const float* __restrict__ query,
                            float* __restrict__ qtf,
                            float* __restrict__ seinp)
{
    int chunk = blockIdx.x >> 6;
    int idx = (blockIdx.x & 63) * 256 + threadIdx.x;   // (b*C+c)
    const float* src = query + (size_t)(chunk * 256) * (BB * CC) + idx;
    float* dst = qtf + (size_t)(chunk * 256) * (BB * CC) + idx;
    float s = 0.f;
    #pragma unroll 8
    for (int n = 0; n < 256; n++) {
        float v = src[(size_t)n * (BB * CC)];
        s += v;
        dst[(size_t)n * (BB * CC)] = tf32r(v);
    }
    seinp[chunk * (BB * CC) + idx] = s;
}

__global__ void se_mlp_kernel(const float* __restrict__ seinp,
                              const float* __restrict__ w1,
                              const float* __restrict__ w2,
                              float* __restrict__ se)
{
    int b = blockIdx.x;
    int tid = threadIdx.x;                       // 256
    __shared__ float xin[256];
    __shared__ float hid[128];
    int idx = b * 256 + tid;
    xin[tid] = (seinp[idx] + seinp[16384 + idx] + seinp[32768 + idx]
              + seinp[49152 + idx]) * (1.0f / (float)NN);
    __syncthreads();
    if (tid < 128) {
        float s = 0.f;
        #pragma unroll 8
        for (int c = 0; c < 256; c++) s += xin[c] * w1[tid * 256 + c];
        hid[tid] = fmaxf(s, 0.f);
    }
    __syncthreads();
    float s = 0.f;
    #pragma unroll 8
    for (int r = 0; r < 128; r++) s += hid[r] * w2[tid * 128 + r];
    se[b * 256 + tid] = 1.f / (1.f + expf(-s));
}

__global__ void ln_kernel(float* __restrict__ x,
                          const float* __restrict__ gg,
                          const float* __restrict__ bb)
{
    int row = blockIdx.x * 8 + (threadIdx.x >> 5);   // 16384 rows of 256
    int lane = threadIdx.x & 31;
    float* xr = x + (size_t)row * 256;
    float4 v0 = ((float4*)xr)[lane];
    float4 v1 = ((float4*)xr)[32 + lane];
    float s  = v0.x + v0.y + v0.z + v0.w + v1.x + v1.y + v1.z + v1.w;
    float sq = v0.x*v0.x + v0.y*v0.y + v0.z*v0.z + v0.w*v0.w
             + v1.x*v1.x + v1.y*v1.y + v1.z*v1.z + v1.w*v1.w;
    #pragma unroll
    for (int o = 16; o > 0; o >>= 1) {
        s  += __shfl_xor_sync(0xffffffffu, s,  o);
        sq += __shfl_xor_sync(0xffffffffu, sq, o);
    }
    float mean = s * (1.f / 256.f);
    float var  = sq * (1.f / 256.f) - mean * mean;
    float rstd = rsqrtf(var + 1e-5f);
    const float4 gA = ((const float4*)gg)[lane];
    const float4 gB = ((const float4*)gg)[32 + lane];
    const float4 bA = ((const float4*)bb)[lane];
    const float4 bB = ((const float4*)bb)[32 + lane];
    float4 r0, r1;
    r0.x = tf32r((v0.x - mean) * rstd * gA.x + bA.x);
    r0.y = tf32r((v0.y - mean) * rstd * gA.y + bA.y);
    r0.z = tf32r((v0.z - mean) * rstd * gA.z + bA.z);
    r0.w = tf32r((v0.w - mean) * rstd * gA.w + bA.w);
    r1.x = tf32r((v1.x - mean) * rstd * gB.x + bB.x);
    r1.y = tf32r((v1.y - mean) * rstd * gB.y + bB.y);
    r1.z = tf32r((v1.z - mean) * rstd * gB.z + bB.z);
    r1.w = tf32r((v1.w - mean) * rstd * gB.w + bB.w);
    ((float4*)xr)[lane] = r0;
    ((float4*)xr)[32 + lane] = r1;
}

// ---------------- kv aggregation: kv[t*32+j][m], ksum[t*32+j] ----------------
__global__ void __launch_bounds__(128) kv_kernel(const float* __restrict__ kbuf,
                                                 const float* __restrict__ vbuf,
                                                 const float* __restrict__ angS,
                                                 float* __restrict__ kvout,
                                                 float* __restrict__ ksumout)
{
    const int bh = blockIdx.x;                 // 512
    const int b = bh >> 3, hh = bh & 7;
    const int tid = threadIdx.x;               // 128
    const int t = tid >> 5, j = tid & 31;
    __shared__ float ksh[8][32];
    __shared__ float vsh[8][32];
    __shared__ float wsh[8][4];
    float acc[32];
    #pragma unroll
    for (int m = 0; m < 32; m++) acc[m] = 0.f;
    float kssum = 0.f;
    const float* kbase = kbuf + (size_t)b * NS * CC + hh * 32;
    const float* vbase = vbuf + (size_t)b * NS * CC + hh * 32;

    for (int s0 = 0; s0 < NS; s0 += 8) {
        {
            int idx = tid & 63, sr = idx >> 3, c4 = idx & 7;
            const float* src = (tid < 64 ? kbase : vbase) + (size_t)(s0 + sr) * CC + c4 * 4;
            float4 v = *(const float4*)src;
            float* dst = (tid < 64) ? &ksh[sr][c4 * 4] : &vsh[sr][c4 * 4];
            dst[0] = v.x; dst[1] = v.y; dst[2] = v.z; dst[3] = v.w;
        }
        if (tid < 32) {
            int sr2 = tid >> 2, tt = tid & 3;
            wsh[sr2][tt] = angS[(s0 + sr2) * 4 + tt];
        }
        __syncthreads();
        #pragma unroll
        for (int sr2 = 0; sr2 < 8; sr2++) {
            float kw = ksh[sr2][j] * wsh[sr2][t];
            kssum += kw;
            #pragma unroll
            for (int m4 = 0; m4 < 8; m4++) {
                float4 vv = *(const float4*)&vsh[sr2][m4 * 4];
                acc[m4 * 4 + 0] += kw * vv.x;
                acc[m4 * 4 + 1] += kw * vv.y;
                acc[m4 * 4 + 2] += kw * vv.z;
                acc[m4 * 4 + 3] += kw * vv.w;
            }
        }
        __syncthreads();
    }
    float* kvdst = kvout + ((size_t)bh * 128 + tid) * 32;
    #pragma unroll
    for (int m4 = 0; m4 < 8; m4++) {
        float4 v;
        v.x = tf32r(acc[m4 * 4 + 0]); v.y = tf32r(acc[m4 * 4 + 1]);
        v.z = tf32r(acc[m4 * 4 + 2]); v.w = tf32r(acc[m4 * 4 + 3]);
        *(float4*)(kvdst + m4 * 4) = v;
    }
    ksumout[(size_t)bh * 128 + tid] = kssum;
}

// ---------------- attention via tensor cores ----------------------------------
__global__ void __launch_bounds__(256, 2) attn_mma_kernel(
    const float* __restrict__ q, const float* __restrict__ kv,
    const float* __restrict__ ksum, const float* __restrict__ angN,
    float* __restrict__ attn)
{
    const int bh = blockIdx.y;                  // 512
    const int b = bh >> 3, hh = bh & 7;
    const int n0 = blockIdx.x * 128;            // 8 tiles
    const int tid  = threadIdx.x;
    const int lane = tid & 31;
    const int wid  = tid >> 5;                  // 0..7
    const int g = lane >> 2, t = lane & 3;
    const int wm = wid * 16;

    __shared__ __align__(16) u32 q_sh[128][36];   // [n][j] tf32 bits
    __shared__ u32 B_sh[4][32][36];               // [t][m][j] tf32 bits (kv transposed)
    __shared__ float ksum_sh[4][32];
    __shared__ float dp_sh[128][4];

    const float* qbase = q + ((size_t)(b * NN + n0)) * CC + hh * 32;
    #pragma unroll
    for (int p = 0; p < 4; p++) {
        int slot = p * 256 + tid;               // 0..1023
        int nl = slot >> 3, jc = slot & 7;
        float4 v = *(const float4*)(qbase + (size_t)nl * CC + jc * 4);
        q_sh[nl][jc * 4 + 0] = __float_as_uint(v.x);
        q_sh[nl][jc * 4 + 1] = __float_as_uint(v.y);
        q_sh[nl][jc * 4 + 2] = __float_as_uint(v.z);
        q_sh[nl][jc * 4 + 3] = __float_as_uint(v.w);
    }
    const float* kvbase = kv + (size_t)bh * 128 * 32;
    #pragma unroll
    for (int p = 0; p < 4; p++) {
        int slot = p * 256 + tid;               // 0..1023
        int d = slot >> 3, mc = slot & 7;       // d = t*32+j
        float4 v = *(const float4*)(kvbase + d * 32 + mc * 4);
        int tt = d >> 5, j = d & 31;
        B_sh[tt][mc * 4 + 0][j] = __float_as_uint(v.x);
        B_sh[tt][mc * 4 + 1][j] = __float_as_uint(v.y);
        B_sh[tt][mc * 4 + 2][j] = __float_as_uint(v.z);
        B_sh[tt][mc * 4 + 3][j] = __float_as_uint(v.w);
    }
    if (tid < 128) ksum_sh[tid >> 5][tid & 31] = ksum[(size_t)bh * 128 + tid];
    __syncthreads();

    // denominator partials: dp[nl][t] = q[nl] . ksum_t  (512 entries, 2/thread)
    #pragma unroll
    for (int e = 0; e < 2; e++) {
        int idx = e * 256 + tid;
        int nl = idx >> 2, tt = idx & 3;
        float s = 0.f;
        #pragma unroll
        for (int j = 0; j < 32; j++)
            s += __uint_as_float(q_sh[nl][j]) * ksum_sh[tt][j];
        dp_sh[nl][tt] = s;
    }
    __syncthreads();

    float acc[4][4][4];                          // [t][nt][c]
    #pragma unroll
    for (int tt = 0; tt < 4; tt++)
        #pragma unroll
        for (int nt = 0; nt < 4; nt++)
            #pragma unroll
            for (int c = 0; c < 4; c++) acc[tt][nt][c] = 0.f;

    #pragma unroll
    for (int kk8 = 0; kk8 < 4; kk8++) {
        int kkk = kk8 * 8;
        u32 afr[4];
        afr[0] = q_sh[wm + g][kkk + t];
        afr[1] = q_sh[wm + g + 8][kkk + t];
        afr[2] = q_sh[wm + g][kkk + t + 4];
        afr[3] = q_sh[wm + g + 8][kkk + t + 4];
        #pragma unroll
        for (int tt = 0; tt < 4; tt++) {
            #pragma unroll
            for (int nt = 0; nt < 4; nt++) {
                u32 bfr[2];
                bfr[0] = B_sh[tt][nt * 8 + g][kkk + t];
                bfr[1] = B_sh[tt][nt * 8 + g][kkk + t + 4];
                mma_tf32(acc[tt][nt], afr, bfr);
            }
        }
    }

    #pragma unroll
    for (int half = 0; half < 2; half++) {
        int nl = wm + g + half * 8;
        int n = n0 + nl;
        float4 w = *(const float4*)(angN + n * 4);
        float den = w.x * dp_sh[nl][0] + w.y * dp_sh[nl][1]
                  + w.z * dp_sh[nl][2] + w.w * dp_sh[nl][3];
        float ad = fminf(fmaxf(fabsf(den), 1e-4f), 1e4f);
        den = (den < 0.f) ? -ad : ad;
        float rden = 1.f / den;
        float* arow = attn + ((size_t)(b * NN + n)) * CC + hh * 32;
        #pragma unroll
        for (int nt = 0; nt < 4; nt++) {
            #pragma unroll
            for (int c2 = 0; c2 < 2; c2++) {
                int ci = half * 2 + c2;
                int col = nt * 8 + t * 2 + c2;
                float num = w.x * acc[0][nt][ci] + w.y * acc[1][nt][ci]
                          + w.z * acc[2][nt][ci] + w.w * acc[3][nt][ci];
                arow[col] = tf32r(num * rden);
            }
        }
    }
}

// ---------------- tf32 tensor-core GEMM with cp.async 3-stage pipeline -------
// Inputs A, Bw MUST already hold tf32-rounded bit patterns.
template<int AMODE>
__device__ __forceinline__ const float* a_index(const float* __restrict__ A, int m, int k, int K)
{
    if (AMODE == 0) {
        return A + (size_t)m * K + k;
    } else if (AMODE == 1) {
        return A + (size_t)(m & (NN - 1)) * (BB * CC) + (m >> 10) * CC + k;
    } else {
        int b = m >> 8, ns = m & 255;
        int dd = k >> 8, i = k & 255;
        int pos = (((ns >> 4) * 2 + (dd >> 1)) << 5) + ((ns & 15) * 2 + (dd & 1));
        return A + (size_t)pos * (BB * CC) + b * CC + i;
    }
}

template<int AMODE, int EMODE>
__global__ void __launch_bounds__(256, 2) mma_gemm_kernel(
    const float* __restrict__ A, const float* __restrict__ Bw,
    const float* __restrict__ bias, float* __restrict__ Cout,
    int M, int N, int K,
    const float* __restrict__ se, float* __restrict__ dout)
{
    __shared__ __align__(16) u32 As[3 * 128][20];   // 3 stages, BK=16, pitch 20
    __shared__ __align__(16) u32 Bs[3 * 128][20];

    const int tid  = threadIdx.x;
    const int lane = tid & 31;
    const int wid  = tid >> 5;
    const int g = lane >> 2;
    const int t = lane & 3;
    const int wm = (wid & 3) * 32;
    const int wn = (wid >> 2) * 64;
    const int m0 = blockIdx.x * 128;
    const int n0 = blockIdx.y * 128;

    const u32 sA = smem_u32(&As[0][0]);
    const u32 sB = smem_u32(&Bs[0][0]);

    float acc[2][8][4];
    #pragma unroll
    for (int mt = 0; mt < 2; mt++)
        #pragma unroll
        for (int nt = 0; nt < 8; nt++)
            #pragma unroll
            for (int c = 0; c < 4; c++) acc[mt][nt][c] = 0.f;

    const int nkt = K >> 4;   // >= 16 for all our GEMMs

    #define ISSUE_STAGE(stage, kt)                                              \
        do {                                                                     \
            _Pragma("unroll")                                                    \
            for (int p = 0; p < 2; p++) {                                        \
                int cch = p * 256 + tid;                                         \
                int row = cch >> 2, kc = cch & 3;                                \
                const float* srcA = a_index<AMODE>(A, m0 + row, (kt) + kc * 4, K); \
                u32 dA = sA + (((stage) * 128 + row) * 20 + kc * 4) * 4;         \
                CP_ASYNC16(dA, srcA);                                            \
                const float* srcB = Bw + (size_t)(n0 + row) * K + (kt) + kc * 4; \
                u32 dB = sB + (((stage) * 128 + row) * 20 + kc * 4) * 4;         \
                CP_ASYNC16(dB, srcB);                                            \
            }                                                                    \
            CP_COMMIT();                                                         \
        } while (0)

    ISSUE_STAGE(0, 0);
    ISSUE_STAGE(1, 16);
    ISSUE_STAGE(2, 32);

    int buf = 0;
    for (int i = 0; i < nkt; i++) {
        CP_WAIT2();
        __syncthreads();
        const int base = buf * 128;
        #pragma unroll
        for (int kk = 0; kk < 16; kk += 8) {
            u32 afr[2][4], bfr[8][2];
            #pragma unroll
            for (int mt = 0; mt < 2; mt++) {
                int row = base + wm + mt * 16;
                afr[mt][0] = As[row + g][kk + t];
                afr[mt][1] = As[row + g + 8][kk + t];
                afr[mt][2] = As[row + g][kk + t + 4];
                afr[mt][3] = As[row + g + 8][kk + t + 4];
            }
            #pragma unroll
            for (int nt = 0; nt < 8; nt++) {
                int col = base + wn + nt * 8 + g;
                bfr[nt][0] = Bs[col][kk + t];
                bfr[nt][1] = Bs[col][kk + t + 4];
            }
            #pragma unroll
            for (int mt = 0; mt < 2; mt++)
                #pragma unroll
                for (int nt = 0; nt < 8; nt++)
                    mma_tf32(acc[mt][nt], afr[mt], bfr[nt]);
        }
        __syncthreads();
        int nx = i + 3;
        if (nx < nkt) {
            ISSUE_STAGE(buf, nx * 16);
        } else {
            CP_COMMIT();   // empty group keeps wait_group accounting in order
        }
        buf = (buf == 2) ? 0 : buf + 1;
    }
    CP_WAIT0();
    #undef ISSUE_STAGE

    // Epilogue
    #pragma unroll
    for (int mt = 0; mt < 2; mt++) {
        #pragma unroll
        for (int half = 0; half < 2; half++) {
            int mrow = m0 + wm + mt * 16 + g + half * 8;
            if (EMODE == 3) {
                int b = mrow >> 10, nseq = mrow & (NN - 1);
                float* drow = dout + ((size_t)nseq * BB + b) * CC;
                const float* serow = se + b * CC;
                #pragma unroll
                for (int nt = 0; nt < 8; nt++) {
                    int col = n0 + wn + nt * 8 + t * 2;
                    float2 o;
                    o.x = (acc[mt][nt][half * 2 + 0] + bias[col])     * serow[col];
                    o.y = (acc[mt][nt][half * 2 + 1] + bias[col + 1]) * serow[col + 1];
                    *(float2*)(drow + col) = o;
                }
            } else if (EMODE == 4) {
                #pragma unroll
                for (int nt = 0; nt < 8; nt++) {
                    int col = n0 + wn + nt * 8 + t * 2;
                    float v0 = acc[mt][nt][half * 2 + 0] + bias[col];
                    float v1 = acc[mt][nt][half * 2 + 1] + bias[col + 1];
                    float2 o;
                    if (col < 256) {
                        o.x = fmaxf(v0, 0.f); o.y = fmaxf(v1, 0.f);
                        *(float2*)(Cout + (size_t)mrow * 256 + col) = o;
                    } else {
                        o.x = v0; o.y = v1;
                        *(float2*)(dout + (size_t)mrow * 256 + col - 256) = o;
                    }
                }
            } else {
                float* crow = Cout + (size_t)mrow * N;
                #pragma unroll
                for (int nt = 0; nt < 8; nt++) {
                    int col = n0 + wn + nt * 8 + t * 2;
                    float v0 = acc[mt][nt][half * 2 + 0] + bias[col];
                    float v1 = acc[mt][nt][half * 2 + 1] + bias[col + 1];
                    if (EMODE == 2) {
                        v0 = tf32r(fmaxf(v0 * QSCALE, 0.f));
                        v1 = tf32r(fmaxf(v1 * QSCALE, 0.f));
                    }
                    float2 o; o.x = v0; o.y = v1;
                    *(float2*)(crow + col) = o;
                }
            }
        }
    }
}

// ---------------- launch ------------------------------------------------------
extern "C" void kernel_launch(void* const* d_in, const int* in_sizes, int n_in,
                              void* d_out, int out_size)
{
    (void)in_sizes; (void)n_in; (void)out_size;
    const float* query = (const float*)d_in[0];
    // d_in[1]=H, d_in[2]=W (always 32), d_in[3]=key, d_in[4]=value : unused
    const float* ipw  = (const float*)d_in[5];
    const float* ipb  = (const float*)d_in[6];
    const float* srw  = (const float*)d_in[7];
    const float* srb  = (const float*)d_in[8];
    const float* ng   = (const float*)d_in[9];
    const float* nb   = (const float*)d_in[10];
    const float* outw = (const float*)d_in[11];
    const float* outb = (const float*)d_in[12];
    const float* sew1 = (const float*)d_in[13];
    const float* sew2 = (const float*)d_in[14];
    float* out = (float*)d_out;

    float *xr, *qb, *kb, *vb, *kv, *ks, *attn, *wt, *se, *sein;
    float *qtf, *ipwtf, *outwtf, *angN, *angS;
    cudaGetSymbolAddress((void**)&xr,     g_xr);
    cudaGetSymbolAddress((void**)&qb,     g_q);
    cudaGetSymbolAddress((void**)&kb,     g_kb);
    cudaGetSymbolAddress((void**)&vb,     g_vb);
    cudaGetSymbolAddress((void**)&kv,     g_kv);
    cudaGetSymbolAddress((void**)&ks,     g_ksum);
    cudaGetSymbolAddress((void**)&attn,   g_attn);
    cudaGetSymbolAddress((void**)&wt,     g_wt);
    cudaGetSymbolAddress((void**)&se,     g_se);
    cudaGetSymbolAddress((void**)&sein,   g_sein);
    cudaGetSymbolAddress((void**)&qtf,    g_qtf);
    cudaGetSymbolAddress((void**)&ipwtf,  g_ipwtf);
    cudaGetSymbolAddress((void**)&outwtf, g_outwtf);
    cudaGetSymbolAddress((void**)&angN,   g_angN);
    cudaGetSymbolAddress((void**)&angS,   g_angS);

    // Side stream + fork/join events (graph-capturable pattern). Created per
    // call; not destroyed (destroying a stream mid-capture invalidates capture).
    cudaStream_t s1;
    cudaStreamCreateWithFlags(&s1, cudaStreamNonBlocking);
    cudaEvent_t evFork, evJoin;
    cudaEventCreateWithFlags(&evFork, cudaEventDisableTiming);
    cudaEventCreateWithFlags(&evJoin, cudaEventDisableTiming);

    // prep (weights, angles) + fused query round/mean — main stream
    prep_kernel<<<2052, 256>>>(ipw, outw, srw, ipwtf, outwtf, wt, angN, angS);
    cvtq_kernel<<<256, 256>>>(query, qtf, sein);
    cudaEventRecord(evFork, 0);

    // side stream: conv chain -> kv aggregation
    cudaStreamWaitEvent(s1, evFork, 0);
    mma_gemm_kernel<2, 0><<<dim3(128, 2), 256, 0, s1>>>(qtf, wt, srb, xr,
                                                        BB * NS, CC, 1024, nullptr, nullptr);
    ln_kernel<<<2048, 256, 0, s1>>>(xr, ng, nb);
    mma_gemm_kernel<0, 4><<<dim3(128, 4), 256, 0, s1>>>(xr, ipwtf + CC * CC, ipb + CC, kb,
                                                        BB * NS, 512, CC, nullptr, vb);
    kv_kernel<<<512, 128, 0, s1>>>(kb, vb, angS, kv, ks);
    cudaEventRecord(evJoin, s1);

    // main stream: SE gate + q projection (concurrent with side chain)
    se_mlp_kernel<<<64, 256>>>(sein, sew1, sew2, se);
    mma_gemm_kernel<1, 2><<<dim3(512, 2), 256>>>(qtf, ipwtf, ipb, qb,
                                                 BB * NN, CC, CC, nullptr, nullptr);

    // join, then attention + output projection
    cudaStreamWaitEvent(0, evJoin, 0);
    attn_mma_kernel<<<dim3(8, 512), 256>>>(qb, kv, ks, angN, attn);
    mma_gemm_kernel<0, 3><<<dim3(512, 2), 256>>>(attn, outwtf, outb, nullptr,
                                                 BB * NN, CC, CC, se, out);
}

// round 6
// speedup vs baseline: 2.6656x; 1.0172x over previous
#include <cuda_runtime.h>
#include <cuda_bf16.h>
#include <math.h>
#include <cstdint>

// Problem constants (fixed by setup_inputs): N=1024, B=64, C=256, h=8, hd=32,
// H=W=32, SR=2 -> Hs=Ws=16, Ns=256.
#define NN 1024
#define BB 64
#define CC 256
#define NHEAD 8
#define HD 32
#define NS 256
#define PI_OVER_64 0.04908738521234052f   // (pi/2)/32
#define PI_OVER_32 0.09817477042468103f   // (pi/2)/16
#define QSCALE 0.17677669529663687f       // 32^-0.5

typedef unsigned int u32;

// ---------------- device scratch (allocation-free: module-load static) -------
__device__ float g_xr[BB * NS * CC];          // conv output -> layernormed (tf32-rounded)
__device__ float g_q[BB * NN * CC];           // q projection, relu'd, tf32-rounded
__device__ float g_kb[BB * NS * CC];          // k projection, relu'd
__device__ float g_vb[BB * NS * CC];          // v projection
__device__ float g_kv[BB * NHEAD * 128 * 32]; // per (b,h): kv[d=t*32+j][m], tf32-rounded
__device__ float g_ksum[BB * NHEAD * 128];    // per (b,h): ksum[d]
__device__ float g_attn[BB * NN * CC];        // attention output, tf32-rounded
__device__ float g_wt[CC * 1024];             // conv weights permuted (O, dd, I), tf32
__device__ float g_se[BB * CC];               // SE gate
__device__ float g_sein[4 * BB * CC];         // partial sums over n-chunks
__device__ float g_qtf[BB * NN * CC];         // query, tf32-rounded, TRANSPOSED (B,N,C)
__device__ float g_ipwtf[3 * CC * CC];        // in_proj_weight, tf32-rounded
__device__ float g_outwtf[CC * CC];           // out_w, tf32-rounded
__device__ float g_angN[NN * 4];              // per n: cos_a, sin_a, cos_b, sin_b
__device__ float g_angS[NS * 4];              // per s (downsampled)

// ---------------- helpers -----------------------------------------------------
__device__ __forceinline__ u32 f2tf32(float x)
{
    u32 r;
    asm("cvt.rna.tf32.f32 %0, %1;" : "=r"(r) : "f"(x));
    return r;
}
__device__ __forceinline__ float tf32r(float x) { return __uint_as_float(f2tf32(x)); }

__device__ __forceinline__ void mma_tf32(float* c, const u32* a, const u32* b)
{
    asm volatile(
        "mma.sync.aligned.m16n8k8.row.col.f32.tf32.tf32.f32 "
        "{%0,%1,%2,%3}, {%4,%5,%6,%7}, {%8,%9}, {%0,%1,%2,%3};"
        : "+f"(c[0]), "+f"(c[1]), "+f"(c[2]), "+f"(c[3])
        : "r"(a[0]), "r"(a[1]), "r"(a[2]), "r"(a[3]),
          "r"(b[0]), "r"(b[1]));
}

__device__ __forceinline__ u32 smem_u32(const void* p)
{
    u32 a;
    asm("{ .reg .u64 t; cvta.to.shared.u64 t, %1; cvt.u32.u64 %0, t; }"
        : "=r"(a) : "l"(p));
    return a;
}

#define CP_ASYNC16(dst, src) \
    asm volatile("cp.async.cg.shared.global [%0], [%1], 16;" :: "r"(dst), "l"(src))
#define CP_COMMIT() asm volatile("cp.async.commit_group;")
#define CP_WAIT2()  asm volatile("cp.async.wait_group 2;")
#define CP_WAIT0()  asm volatile("cp.async.wait_group 0;")

// ---------------- fused prep: ipw cvt | outw cvt | wtrans | angles -----------
__global__ void prep_kernel(const float* __restrict__ ipw,
                            const float* __restrict__ outw,
                            const float* __restrict__ srw,
                            float* __restrict__ ipwtf,
                            float* __restrict__ outwtf,
                            float* __restrict__ wt,
                            float* __restrict__ angN,
                            float* __restrict__ angS)
{
    int bid = blockIdx.x;
    int tid = threadIdx.x;
    if (bid < 768) {                             // ipw: 196608 elems
        int i = bid * 256 + tid;
        ipwtf[i] = tf32r(ipw[i]);
    } else if (bid < 1024) {                     // outw: 65536
        int i = (bid - 768) * 256 + tid;
        outwtf[i] = tf32r(outw[i]);
    } else if (bid < 2048) {                     // wtrans: 262144
        int idx = (bid - 1024) * 256 + tid;
        int o = idx >> 10, rest = idx & 1023;
        int dd = rest >> 8, i = rest & 255;
        wt[idx] = tf32r(srw[(o << 10) + (i << 2) + dd]);
    } else {                                     // angles: 1024
        int n = (bid - 2048) * 256 + tid;
        {
            float a = (float)(n >> 5) * PI_OVER_64;
            float b = (float)(n & 31) * PI_OVER_64;
            float sa, ca, sb, cb;
            sincosf(a, &sa, &ca);
            sincosf(b, &sb, &cb);
            float4 w; w.x = ca; w.y = sa; w.z = cb; w.w = sb;
            *(float4*)(angN + n * 4) = w;
        }
        if (n < NS) {
            float a = (float)(n >> 4) * PI_OVER_32;
            float b = (float)(n & 15) * PI_OVER_32;
            float sa, ca, sb, cb;
            sincosf(a, &sa, &ca);
            sincosf(b, &sb, &cb);
            float4 w; w.x = ca; w.y = sa; w.z = cb; w.w = sb;
            *(float4*)(angS + n * 4) = w;
        }
    }
}

// ---------------- fused query tf32-round + TRANSPOSE + column partial mean ---
// grid 256: blockIdx = chunk*64 + colblk; thread owns column idx=(b,c),
// loops n in [chunk*256, chunk*256+256). Writes qtf in (B,N,C) layout.
__global__ void cvtq_kernel(const float* __restrict__ query,
                            float* __restrict__ qtf,
                            float* __restrict__ seinp)
{
    int chunk = blockIdx.x >> 6;
    int idx = (blockIdx.x & 63) * 256 + threadIdx.x;   // (b*C+c)
    int b = idx >> 8, c = idx & 255;
    int nbase = chunk * 256;
    const float* src = query + (size_t)nbase * (BB * CC) + idx;
    float* dst = qtf + ((size_t)b * NN + nbase) * CC + c;
    float s = 0.f;
    #pragma unroll 8
    for (int n = 0; n < 256; n++) {
        float v = src[(size_t)n * (BB * CC)];
        s += v;
        dst[(size_t)n * CC] = tf32r(v);
    }
    seinp[chunk * (BB * CC) + idx] = s;
}

__global__ void se_mlp_kernel(const float* __restrict__ seinp,
                              const float* __restrict__ w1,
                              const float* __restrict__ w2,
                              float* __restrict__ se)
{
    int b = blockIdx.x;
    int tid = threadIdx.x;                       // 256
    __shared__ float xin[256];
    __shared__ float hid[128];
    int idx = b * 256 + tid;
    xin[tid] = (seinp[idx] + seinp[16384 + idx] + seinp[32768 + idx]
              + seinp[49152 + idx]) * (1.0f / (float)NN);
    __syncthreads();
    if (tid < 128) {
        float s = 0.f;
        #pragma unroll 8
        for (int c = 0; c < 256; c++) s += xin[c] * w1[tid * 256 + c];
        hid[tid] = fmaxf(s, 0.f);
    }
    __syncthreads();
    float s = 0.f;
    #pragma unroll 8
    for (int r = 0; r < 128; r++) s += hid[r] * w2[tid * 128 + r];
    se[b * 256 + tid] = 1.f / (1.f + expf(-s));
}

__global__ void ln_kernel(float* __restrict__ x,
                          const float* __restrict__ gg,
                          const float* __restrict__ bb)
{
    int row = blockIdx.x * 8 + (threadIdx.x >> 5);   // 16384 rows of 256
    int lane = threadIdx.x & 31;
    float* xr = x + (size_t)row * 256;
    float4 v0 = ((float4*)xr)[lane];
    float4 v1 = ((float4*)xr)[32 + lane];
    float s  = v0.x + v0.y + v0.z + v0.w + v1.x + v1.y + v1.z + v1.w;
    float sq = v0.x*v0.x + v0.y*v0.y + v0.z*v0.z + v0.w*v0.w
             + v1.x*v1.x + v1.y*v1.y + v1.z*v1.z + v1.w*v1.w;
    #pragma unroll
    for (int o = 16; o > 0; o >>= 1) {
        s  += __shfl_xor_sync(0xffffffffu, s,  o);
        sq += __shfl_xor_sync(0xffffffffu, sq, o);
    }
    float mean = s * (1.f / 256.f);
    float var  = sq * (1.f / 256.f) - mean * mean;
    float rstd = rsqrtf(var + 1e-5f);
    const float4 gA = ((const float4*)gg)[lane];
    const float4 gB = ((const float4*)gg)[32 + lane];
    const float4 bA = ((const float4*)bb)[lane];
    const float4 bB = ((const float4*)bb)[32 + lane];
    float4 r0, r1;
    r0.x = tf32r((v0.x - mean) * rstd * gA.x + bA.x);
    r0.y = tf32r((v0.y - mean) * rstd * gA.y + bA.y);
    r0.z = tf32r((v0.z - mean) * rstd * gA.z + bA.z);
    r0.w = tf32r((v0.w - mean) * rstd * gA.w + bA.w);
    r1.x = tf32r((v1.x - mean) * rstd * gB.x + bB.x);
    r1.y = tf32r((v1.y - mean) * rstd * gB.y + bB.y);
    r1.z = tf32r((v1.z - mean) * rstd * gB.z + bB.z);
    r1.w = tf32r((v1.w - mean) * rstd * gB.w + bB.w);
    ((float4*)xr)[lane] = r0;
    ((float4*)xr)[32 + lane] = r1;
}

// ---------------- kv aggregation: kv[t*32+j][m], ksum[t*32+j] ----------------
__global__ void __launch_bounds__(128) kv_kernel(const float* __restrict__ kbuf,
                                                 const float* __restrict__ vbuf,
                                                 const float* __restrict__ angS,
                                                 float* __restrict__ kvout,
                                                 float* __restrict__ ksumout)
{
    const int bh = blockIdx.x;                 // 512
    const int b = bh >> 3, hh = bh & 7;
    const int tid = threadIdx.x;               // 128
    const int t = tid >> 5, j = tid & 31;
    __shared__ float ksh[8][32];
    __shared__ float vsh[8][32];
    __shared__ float wsh[8][4];
    float acc[32];
    #pragma unroll
    for (int m = 0; m < 32; m++) acc[m] = 0.f;
    float kssum = 0.f;
    const float* kbase = kbuf + (size_t)b * NS * CC + hh * 32;
    const float* vbase = vbuf + (size_t)b * NS * CC + hh * 32;

    for (int s0 = 0; s0 < NS; s0 += 8) {
        {
            int idx = tid & 63, sr = idx >> 3, c4 = idx & 7;
            const float* src = (tid < 64 ? kbase : vbase) + (size_t)(s0 + sr) * CC + c4 * 4;
            float4 v = *(const float4*)src;
            float* dst = (tid < 64) ? &ksh[sr][c4 * 4] : &vsh[sr][c4 * 4];
            dst[0] = v.x; dst[1] = v.y; dst[2] = v.z; dst[3] = v.w;
        }
        if (tid < 32) {
            int sr2 = tid >> 2, tt = tid & 3;
            wsh[sr2][tt] = angS[(s0 + sr2) * 4 + tt];
        }
        __syncthreads();
        #pragma unroll
        for (int sr2 = 0; sr2 < 8; sr2++) {
            float kw = ksh[sr2][j] * wsh[sr2][t];
            kssum += kw;
            #pragma unroll
            for (int m4 = 0; m4 < 8; m4++) {
                float4 vv = *(const float4*)&vsh[sr2][m4 * 4];
                acc[m4 * 4 + 0] += kw * vv.x;
                acc[m4 * 4 + 1] += kw * vv.y;
                acc[m4 * 4 + 2] += kw * vv.z;
                acc[m4 * 4 + 3] += kw * vv.w;
            }
        }
        __syncthreads();
    }
    float* kvdst = kvout + ((size_t)bh * 128 + tid) * 32;
    #pragma unroll
    for (int m4 = 0; m4 < 8; m4++) {
        float4 v;
        v.x = tf32r(acc[m4 * 4 + 0]); v.y = tf32r(acc[m4 * 4 + 1]);
        v.z = tf32r(acc[m4 * 4 + 2]); v.w = tf32r(acc[m4 * 4 + 3]);
        *(float4*)(kvdst + m4 * 4) = v;
    }
    ksumout[(size_t)bh * 128 + tid] = kssum;
}

// ---------------- attention via tensor cores ----------------------------------
__global__ void __launch_bounds__(256, 2) attn_mma_kernel(
    const float* __restrict__ q, const float* __restrict__ kv,
    const float* __restrict__ ksum, const float* __restrict__ angN,
    float* __restrict__ attn)
{
    const int bh = blockIdx.y;                  // 512
    const int b = bh >> 3, hh = bh & 7;
    const int n0 = blockIdx.x * 128;            // 8 tiles
    const int tid  = threadIdx.x;
    const int lane = tid & 31;
    const int wid  = tid >> 5;                  // 0..7
    const int g = lane >> 2, t = lane & 3;
    const int wm = wid * 16;

    __shared__ __align__(16) u32 q_sh[128][36];   // [n][j] tf32 bits
    __shared__ u32 B_sh[4][32][36];               // [t][m][j] tf32 bits (kv transposed)
    __shared__ float ksum_sh[4][32];
    __shared__ float dp_sh[128][4];

    const float* qbase = q + ((size_t)(b * NN + n0)) * CC + hh * 32;
    #pragma unroll
    for (int p = 0; p < 4; p++) {
        int slot = p * 256 + tid;               // 0..1023
        int nl = slot >> 3, jc = slot & 7;
        float4 v = *(const float4*)(qbase + (size_t)nl * CC + jc * 4);
        q_sh[nl][jc * 4 + 0] = __float_as_uint(v.x);
        q_sh[nl][jc * 4 + 1] = __float_as_uint(v.y);
        q_sh[nl][jc * 4 + 2] = __float_as_uint(v.z);
        q_sh[nl][jc * 4 + 3] = __float_as_uint(v.w);
    }
    const float* kvbase = kv + (size_t)bh * 128 * 32;
    #pragma unroll
    for (int p = 0; p < 4; p++) {
        int slot = p * 256 + tid;               // 0..1023
        int d = slot >> 3, mc = slot & 7;       // d = t*32+j
        float4 v = *(const float4*)(kvbase + d * 32 + mc * 4);
        int tt = d >> 5, j = d & 31;
        B_sh[tt][mc * 4 + 0][j] = __float_as_uint(v.x);
        B_sh[tt][mc * 4 + 1][j] = __float_as_uint(v.y);
        B_sh[tt][mc * 4 + 2][j] = __float_as_uint(v.z);
        B_sh[tt][mc * 4 + 3][j] = __float_as_uint(v.w);
    }
    if (tid < 128) ksum_sh[tid >> 5][tid & 31] = ksum[(size_t)bh * 128 + tid];
    __syncthreads();

    // denominator partials: dp[nl][t] = q[nl] . ksum_t  (512 entries, 2/thread)
    #pragma unroll
    for (int e = 0; e < 2; e++) {
        int idx = e * 256 + tid;
        int nl = idx >> 2, tt = idx & 3;
        float s = 0.f;
        #pragma unroll
        for (int j = 0; j < 32; j++)
            s += __uint_as_float(q_sh[nl][j]) * ksum_sh[tt][j];
        dp_sh[nl][tt] = s;
    }
    __syncthreads();

    float acc[4][4][4];                          // [t][nt][c]
    #pragma unroll
    for (int tt = 0; tt < 4; tt++)
        #pragma unroll
        for (int nt = 0; nt < 4; nt++)
            #pragma unroll
            for (int c = 0; c < 4; c++) acc[tt][nt][c] = 0.f;

    #pragma unroll
    for (int kk8 = 0; kk8 < 4; kk8++) {
        int kkk = kk8 * 8;
        u32 afr[4];
        afr[0] = q_sh[wm + g][kkk + t];
        afr[1] = q_sh[wm + g + 8][kkk + t];
        afr[2] = q_sh[wm + g][kkk + t + 4];
        afr[3] = q_sh[wm + g + 8][kkk + t + 4];
        #pragma unroll
        for (int tt = 0; tt < 4; tt++) {
            #pragma unroll
            for (int nt = 0; nt < 4; nt++) {
                u32 bfr[2];
                bfr[0] = B_sh[tt][nt * 8 + g][kkk + t];
                bfr[1] = B_sh[tt][nt * 8 + g][kkk + t + 4];
                mma_tf32(acc[tt][nt], afr, bfr);
            }
        }
    }

    #pragma unroll
    for (int half = 0; half < 2; half++) {
        int nl = wm + g + half * 8;
        int n = n0 + nl;
        float4 w = *(const float4*)(angN + n * 4);
        float den = w.x * dp_sh[nl][0] + w.y * dp_sh[nl][1]
                  + w.z * dp_sh[nl][2] + w.w * dp_sh[nl][3];
        float ad = fminf(fmaxf(fabsf(den), 1e-4f), 1e4f);
        den = (den < 0.f) ? -ad : ad;
        float rden = 1.f / den;
        float* arow = attn + ((size_t)(b * NN + n)) * CC + hh * 32;
        #pragma unroll
        for (int nt = 0; nt < 4; nt++) {
            #pragma unroll
            for (int c2 = 0; c2 < 2; c2++) {
                int ci = half * 2 + c2;
                int col = nt * 8 + t * 2 + c2;
                float num = w.x * acc[0][nt][ci] + w.y * acc[1][nt][ci]
                          + w.z * acc[2][nt][ci] + w.w * acc[3][nt][ci];
                arow[col] = tf32r(num * rden);
            }
        }
    }
}

// ---------------- tf32 tensor-core GEMM with cp.async 3-stage pipeline -------
// Inputs A, Bw MUST already hold tf32-rounded bit patterns.
// AMODE: 0 plain row-major A (row length = K);
//        2 implicit conv patches from qtf in (B,N,C) layout: m=(b,ns), k=(dd,i).
template<int AMODE>
__device__ __forceinline__ const float* a_index(const float* __restrict__ A, int m, int k, int K)
{
    if (AMODE == 0) {
        return A + (size_t)m * K + k;
    } else {
        int b = m >> 8, ns = m & 255;
        int dd = k >> 8, i = k & 255;
        int pos = (((ns >> 4) * 2 + (dd >> 1)) << 5) + ((ns & 15) * 2 + (dd & 1));
        return A + ((size_t)(b << 10) + pos) * CC + i;
    }
}

template<int AMODE, int EMODE>
__global__ void __launch_bounds__(256, 2) mma_gemm_kernel(
    const float* __restrict__ A, const float* __restrict__ Bw,
    const float* __restrict__ bias, float* __restrict__ Cout,
    int M, int N, int K,
    const float* __restrict__ se, float* __restrict__ dout)
{
    __shared__ __align__(16) u32 As[3 * 128][20];   // 3 stages, BK=16, pitch 20
    __shared__ __align__(16) u32 Bs[3 * 128][20];

    const int tid  = threadIdx.x;
    const int lane = tid & 31;
    const int wid  = tid >> 5;
    const int g = lane >> 2;
    const int t = lane & 3;
    const int wm = (wid & 3) * 32;
    const int wn = (wid >> 2) * 64;
    const int m0 = blockIdx.x * 128;
    const int n0 = blockIdx.y * 128;

    const u32 sA = smem_u32(&As[0][0]);
    const u32 sB = smem_u32(&Bs[0][0]);

    float acc[2][8][4];
    #pragma unroll
    for (int mt = 0; mt < 2; mt++)
        #pragma unroll
        for (int nt = 0; nt < 8; nt++)
            #pragma unroll
            for (int c = 0; c < 4; c++) acc[mt][nt][c] = 0.f;

    const int nkt = K >> 4;

    #define ISSUE_STAGE(stage, kt)                                              \
        do {                                                                     \
            _Pragma("unroll")                                                    \
            for (int p = 0; p < 2; p++) {                                        \
                int cch = p * 256 + tid;                                         \
                int row = cch >> 2, kc = cch & 3;                                \
                const float* srcA = a_index<AMODE>(A, m0 + row, (kt) + kc * 4, K); \
                u32 dA = sA + (((stage) * 128 + row) * 20 + kc * 4) * 4;         \
                CP_ASYNC16(dA, srcA);                                            \
                const float* srcB = Bw + (size_t)(n0 + row) * K + (kt) + kc * 4; \
                u32 dB = sB + (((stage) * 128 + row) * 20 + kc * 4) * 4;         \
                CP_ASYNC16(dB, srcB);                                            \
            }                                                                    \
            CP_COMMIT();                                                         \
        } while (0)

    ISSUE_STAGE(0, 0);
    ISSUE_STAGE(1, 16);
    ISSUE_STAGE(2, 32);

    int buf = 0;
    for (int i = 0; i < nkt; i++) {
        CP_WAIT2();
        __syncthreads();
        const int base = buf * 128;
        #pragma unroll
        for (int kk = 0; kk < 16; kk += 8) {
            u32 afr[2][4], bfr[8][2];
            #pragma unroll
            for (int mt = 0; mt < 2; mt++) {
                int row = base + wm + mt * 16;
                afr[mt][0] = As[row + g][kk + t];
                afr[mt][1] = As[row + g + 8][kk + t];
                afr[mt][2] = As[row + g][kk + t + 4];
                afr[mt][3] = As[row + g + 8][kk + t + 4];
            }
            #pragma unroll
            for (int nt = 0; nt < 8; nt++) {
                int col = base + wn + nt * 8 + g;
                bfr[nt][0] = Bs[col][kk + t];
                bfr[nt][1] = Bs[col][kk + t + 4];
            }
            #pragma unroll
            for (int mt = 0; mt < 2; mt++)
                #pragma unroll
                for (int nt = 0; nt < 8; nt++)
                    mma_tf32(acc[mt][nt], afr[mt], bfr[nt]);
        }
        __syncthreads();
        int nx = i + 3;
        if (nx < nkt) {
            ISSUE_STAGE(buf, nx * 16);
        } else {
            CP_COMMIT();   // empty group keeps wait_group accounting in order
        }
        buf = (buf == 2) ? 0 : buf + 1;
    }
    CP_WAIT0();
    #undef ISSUE_STAGE

    // Epilogue
    #pragma unroll
    for (int mt = 0; mt < 2; mt++) {
        #pragma unroll
        for (int half = 0; half < 2; half++) {
            int mrow = m0 + wm + mt * 16 + g + half * 8;
            if (EMODE == 3) {
                int b = mrow >> 10, nseq = mrow & (NN - 1);
                float* drow = dout + ((size_t)nseq * BB + b) * CC;
                const float* serow = se + b * CC;
                #pragma unroll
                for (int nt = 0; nt < 8; nt++) {
                    int col = n0 + wn + nt * 8 + t * 2;
                    float2 o;
                    o.x = (acc[mt][nt][half * 2 + 0] + bias[col])     * serow[col];
                    o.y = (acc[mt][nt][half * 2 + 1] + bias[col + 1]) * serow[col + 1];
                    *(float2*)(drow + col) = o;
                }
            } else if (EMODE == 4) {
                #pragma unroll
                for (int nt = 0; nt < 8; nt++) {
                    int col = n0 + wn + nt * 8 + t * 2;
                    float v0 = acc[mt][nt][half * 2 + 0] + bias[col];
                    float v1 = acc[mt][nt][half * 2 + 1] + bias[col + 1];
                    float2 o;
                    if (col < 256) {
                        o.x = fmaxf(v0, 0.f); o.y = fmaxf(v1, 0.f);
                        *(float2*)(Cout + (size_t)mrow * 256 + col) = o;
                    } else {
                        o.x = v0; o.y = v1;
                        *(float2*)(dout + (size_t)mrow * 256 + col - 256) = o;
                    }
                }
            } else {
                float* crow = Cout + (size_t)mrow * N;
                #pragma unroll
                for (int nt = 0; nt < 8; nt++) {
                    int col = n0 + wn + nt * 8 + t * 2;
                    float v0 = acc[mt][nt][half * 2 + 0] + bias[col];
                    float v1 = acc[mt][nt][half * 2 + 1] + bias[col + 1];
                    if (EMODE == 2) {
                        v0 = tf32r(fmaxf(v0 * QSCALE, 0.f));
                        v1 = tf32r(fmaxf(v1 * QSCALE, 0.f));
                    }
                    float2 o; o.x = v0; o.y = v1;
                    *(float2*)(crow + col) = o;
                }
            }
        }
    }
}

// ---------------- launch ------------------------------------------------------
extern "C" void kernel_launch(void* const* d_in, const int* in_sizes, int n_in,
                              void* d_out, int out_size)
{
    (void)in_sizes; (void)n_in; (void)out_size;
    const float* query = (const float*)d_in[0];
    // d_in[1]=H, d_in[2]=W (always 32), d_in[3]=key, d_in[4]=value : unused
    const float* ipw  = (const float*)d_in[5];
    const float* ipb  = (const float*)d_in[6];
    const float* srw  = (const float*)d_in[7];
    const float* srb  = (const float*)d_in[8];
    const float* ng   = (const float*)d_in[9];
    const float* nb   = (const float*)d_in[10];
    const float* outw = (const float*)d_in[11];
    const float* outb = (const float*)d_in[12];
    const float* sew1 = (const float*)d_in[13];
    const float* sew2 = (const float*)d_in[14];
    float* out = (float*)d_out;

    float *xr, *qb, *kb, *vb, *kv, *ks, *attn, *wt, *se, *sein;
    float *qtf, *ipwtf, *outwtf, *angN, *angS;
    cudaGetSymbolAddress((void**)&xr,     g_xr);
    cudaGetSymbolAddress((void**)&qb,     g_q);
    cudaGetSymbolAddress((void**)&kb,     g_kb);
    cudaGetSymbolAddress((void**)&vb,     g_vb);
    cudaGetSymbolAddress((void**)&kv,     g_kv);
    cudaGetSymbolAddress((void**)&ks,     g_ksum);
    cudaGetSymbolAddress((void**)&attn,   g_attn);
    cudaGetSymbolAddress((void**)&wt,     g_wt);
    cudaGetSymbolAddress((void**)&se,     g_se);
    cudaGetSymbolAddress((void**)&sein,   g_sein);
    cudaGetSymbolAddress((void**)&qtf,    g_qtf);
    cudaGetSymbolAddress((void**)&ipwtf,  g_ipwtf);
    cudaGetSymbolAddress((void**)&outwtf, g_outwtf);
    cudaGetSymbolAddress((void**)&angN,   g_angN);
    cudaGetSymbolAddress((void**)&angS,   g_angS);

    // Side stream + fork/join events (graph-capturable pattern). Created per
    // call; not destroyed (destroying a stream mid-capture invalidates capture).
    cudaStream_t s1;
    cudaStreamCreateWithFlags(&s1, cudaStreamNonBlocking);
    cudaEvent_t evStart, evPrep, evQ, evJoin;
    cudaEventCreateWithFlags(&evStart, cudaEventDisableTiming);
    cudaEventCreateWithFlags(&evPrep,  cudaEventDisableTiming);
    cudaEventCreateWithFlags(&evQ,     cudaEventDisableTiming);
    cudaEventCreateWithFlags(&evJoin,  cudaEventDisableTiming);

    // fork: prep on side stream, cvtq on main stream — concurrent
    cudaEventRecord(evStart, 0);
    cudaStreamWaitEvent(s1, evStart, 0);
    prep_kernel<<<2052, 256, 0, s1>>>(ipw, outw, srw, ipwtf, outwtf, wt, angN, angS);
    cudaEventRecord(evPrep, s1);

    cvtq_kernel<<<256, 256>>>(query, qtf, sein);
    cudaEventRecord(evQ, 0);

    // side stream: conv chain -> kv aggregation (needs prep + qtf)
    cudaStreamWaitEvent(s1, evQ, 0);
    mma_gemm_kernel<2, 0><<<dim3(128, 2), 256, 0, s1>>>(qtf, wt, srb, xr,
                                                        BB * NS, CC, 1024, nullptr, nullptr);
    ln_kernel<<<2048, 256, 0, s1>>>(xr, ng, nb);
    mma_gemm_kernel<0, 4><<<dim3(128, 4), 256, 0, s1>>>(xr, ipwtf + CC * CC, ipb + CC, kb,
                                                        BB * NS, 512, CC, nullptr, vb);
    kv_kernel<<<512, 128, 0, s1>>>(kb, vb, angS, kv, ks);
    cudaEventRecord(evJoin, s1);

    // main stream: SE gate + q projection (needs prep for ipwtf)
    cudaStreamWaitEvent(0, evPrep, 0);
    se_mlp_kernel<<<64, 256>>>(sein, sew1, sew2, se);
    mma_gemm_kernel<0, 2><<<dim3(512, 2), 256>>>(qtf, ipwtf, ipb, qb,
                                                 BB * NN, CC, CC, nullptr, nullptr);

    // join, then attention + output projection
    cudaStreamWaitEvent(0, evJoin, 0);
    attn_mma_kernel<<<dim3(8, 512), 256>>>(qb, kv, ks, angN, attn);
    mma_gemm_kernel<0, 3><<<dim3(512, 2), 256>>>(attn, outwtf, outb, nullptr,
                                                 BB * NN, CC, CC, se, out);
}